// round 2
// baseline (speedup 1.0000x reference)
#include <cuda_runtime.h>
#include <cuda_bf16.h>
#include <math.h>

// Problem constants
#define BB    2
#define S_LEN 2048
#define HID   2304
#define NH    8
#define NKVH  4
#define DH    256
#define MROWS (BB * S_LEN)        // 4096
#define QCOLS (NH * DH)           // 2048
#define KCOLS (NKVH * DH)         // 1024
#define WINDOW 1024
#define SCALING 0.0625f           // 256^-0.5
#define SOFTCAP 50.0f

// Scratch (static device globals; no runtime allocation allowed)
__device__ float g_q [(size_t)MROWS * QCOLS];   // 32 MB
__device__ float g_k [(size_t)MROWS * KCOLS];   // 16 MB
__device__ float g_v [(size_t)MROWS * KCOLS];   // 16 MB
__device__ float g_ao[(size_t)MROWS * QCOLS];   // 32 MB
__device__ float g_cos[S_LEN * (DH/2)];         // 1 MB
__device__ float g_sin[S_LEN * (DH/2)];         // 1 MB

// ---------------------------------------------------------------------------
// RoPE table: cos/sin per (position, freq). double pow -> float to track the
// jnp float32 computation closely.
// ---------------------------------------------------------------------------
__global__ void rope_table_kernel(const int* __restrict__ pos,
                                  float* __restrict__ cs, float* __restrict__ sn) {
    int idx = blockIdx.x * blockDim.x + threadIdx.x;
    if (idx >= S_LEN * (DH/2)) return;
    int s = idx >> 7;         // / 128
    int j = idx & 127;
    double invf = pow(10000.0, -(double)j / 128.0);
    float freq = (float)pos[s] * (float)invf;
    cs[idx] = cosf(freq);
    sn[idx] = sinf(freq);
}

// ---------------------------------------------------------------------------
// RoPE apply (in place) on x of shape (MROWS, nh*256)
// pair (j, j+128) within each head.
// ---------------------------------------------------------------------------
__global__ void rope_apply_kernel(float* __restrict__ x,
                                  const float* __restrict__ cs,
                                  const float* __restrict__ sn, int nh) {
    int total = MROWS * nh * 128;
    int idx = blockIdx.x * blockDim.x + threadIdx.x;
    if (idx >= total) return;
    int per_row = nh * 128;
    int mrow = idx / per_row;
    int rp   = idx - mrow * per_row;
    int hh = rp >> 7;
    int j  = rp & 127;
    int s = mrow & (S_LEN - 1);           // m % S
    float c  = cs[s * 128 + j];
    float sv = sn[s * 128 + j];
    size_t base = (size_t)mrow * (nh * 256) + hh * 256 + j;
    float x1 = x[base];
    float x2 = x[base + 128];
    x[base]       = x1 * c - x2 * sv;
    x[base + 128] = x2 * c + x1 * sv;
}

// ---------------------------------------------------------------------------
// GEMM (NT): C[M,N] = A[M,K] (row-major) * B[N,K]^T (row-major, K contiguous)
// 128x128 tile, BK=16, 256 threads, 8x8 microtile. All dims divisible.
// ---------------------------------------------------------------------------
__global__ __launch_bounds__(256) void gemm_nt_kernel(
    const float* __restrict__ A, const float* __restrict__ B,
    float* __restrict__ C, int M, int N, int K)
{
    __shared__ __align__(16) float As[16][132];
    __shared__ __align__(16) float Bs[16][132];

    int tid = threadIdx.x;
    int m0 = blockIdx.y * 128;
    int n0 = blockIdx.x * 128;
    int tr = tid >> 4;          // 0..15
    int tc = tid & 15;          // 0..15
    int rm = tr * 8;
    int cn = tc * 8;

    float acc[8][8];
#pragma unroll
    for (int i = 0; i < 8; i++)
#pragma unroll
        for (int j = 0; j < 8; j++) acc[i][j] = 0.f;

    int lrow = tid >> 2;        // 0..63
    int lk4  = (tid & 3) * 4;   // 0,4,8,12

#pragma unroll 1
    for (int k0 = 0; k0 < K; k0 += 16) {
        __syncthreads();
#pragma unroll
        for (int rep = 0; rep < 2; rep++) {
            int row = rep * 64 + lrow;
            float4 av = *(const float4*)(A + (size_t)(m0 + row) * K + k0 + lk4);
            As[lk4 + 0][row] = av.x; As[lk4 + 1][row] = av.y;
            As[lk4 + 2][row] = av.z; As[lk4 + 3][row] = av.w;
            float4 bv = *(const float4*)(B + (size_t)(n0 + row) * K + k0 + lk4);
            Bs[lk4 + 0][row] = bv.x; Bs[lk4 + 1][row] = bv.y;
            Bs[lk4 + 2][row] = bv.z; Bs[lk4 + 3][row] = bv.w;
        }
        __syncthreads();
#pragma unroll
        for (int kk = 0; kk < 16; kk++) {
            float a[8], b[8];
            float4 a0 = *(const float4*)(&As[kk][rm]);
            float4 a1 = *(const float4*)(&As[kk][rm + 4]);
            a[0]=a0.x; a[1]=a0.y; a[2]=a0.z; a[3]=a0.w;
            a[4]=a1.x; a[5]=a1.y; a[6]=a1.z; a[7]=a1.w;
            float4 b0 = *(const float4*)(&Bs[kk][cn]);
            float4 b1 = *(const float4*)(&Bs[kk][cn + 4]);
            b[0]=b0.x; b[1]=b0.y; b[2]=b0.z; b[3]=b0.w;
            b[4]=b1.x; b[5]=b1.y; b[6]=b1.z; b[7]=b1.w;
#pragma unroll
            for (int i = 0; i < 8; i++)
#pragma unroll
                for (int j = 0; j < 8; j++)
                    acc[i][j] += a[i] * b[j];
        }
    }

#pragma unroll
    for (int i = 0; i < 8; i++) {
        float4 c0 = make_float4(acc[i][0], acc[i][1], acc[i][2], acc[i][3]);
        float4 c1 = make_float4(acc[i][4], acc[i][5], acc[i][6], acc[i][7]);
        float* crow = C + (size_t)(m0 + rm + i) * N + n0 + cn;
        *(float4*)(crow)     = c0;
        *(float4*)(crow + 4) = c1;
    }
}

// ---------------------------------------------------------------------------
// Flash-style sliding-window attention, fp32.
// Block: 256 threads handles TQ=32 query rows for one (b, h).
// Thread (w, lane): row r = w*4 + lane/8 in tile, d-chunks c = lane%8
// owning d indices { c*4 + 32*i + t : i in 0..7, t in 0..3 } (strided float4
// so smem reads are conflict-free).
// ---------------------------------------------------------------------------
#define TQ 32
#define TK 16

__global__ __launch_bounds__(256) void attn_kernel(
    const float* __restrict__ q, const float* __restrict__ k,
    const float* __restrict__ v, float* __restrict__ o)
{
    __shared__ __align__(16) float Ks[TK][DH];
    __shared__ __align__(16) float Vs[TK][DH];

    int qt = blockIdx.x;
    int h  = blockIdx.y;
    int b  = blockIdx.z;
    int kvh = h >> 1;                 // n_rep = 2
    int tid = threadIdx.x;
    int lane = tid & 31, w = tid >> 5;
    int r = w * 4 + (lane >> 3);      // 0..31
    int c = lane & 7;                 // 0..7
    int qq = qt * TQ + r;

    // Load Q row fragment into registers
    const float* qrow = q + ((size_t)(b * S_LEN + qq)) * QCOLS + h * DH;
    float qreg[32];
#pragma unroll
    for (int i = 0; i < 8; i++) {
        float4 t = *(const float4*)(qrow + c * 4 + 32 * i);
        qreg[i*4+0]=t.x; qreg[i*4+1]=t.y; qreg[i*4+2]=t.z; qreg[i*4+3]=t.w;
    }

    float acc[32];
#pragma unroll
    for (int i = 0; i < 32; i++) acc[i] = 0.f;
    float m = -INFINITY, l = 0.f;

    int q0 = qt * TQ;
    int kstart = q0 - (WINDOW - 1);
    if (kstart < 0) kstart = 0;
    kstart &= ~(TK - 1);
    int kend = q0 + TQ - 1;

#pragma unroll 1
    for (int kt = kstart; kt <= kend; kt += TK) {
        __syncthreads();
        {
            const float* kbase = k + ((size_t)(b * S_LEN + kt)) * KCOLS + kvh * DH;
            const float* vbase = v + ((size_t)(b * S_LEN + kt)) * KCOLS + kvh * DH;
#pragma unroll
            for (int p = 0; p < 4; p++) {
                int idx  = p * 256 + tid;      // float4 index (0..1023)
                int row  = idx >> 6;
                int col4 = idx & 63;
                *(float4*)(&Ks[row][col4 * 4]) =
                    *(const float4*)(kbase + (size_t)row * KCOLS + col4 * 4);
                *(float4*)(&Vs[row][col4 * 4]) =
                    *(const float4*)(vbase + (size_t)row * KCOLS + col4 * 4);
            }
        }
        __syncthreads();

        // scores for this tile
        float sc[TK];
        float tmax = -INFINITY;
#pragma unroll
        for (int j = 0; j < TK; j++) {
            float part = 0.f;
#pragma unroll
            for (int i = 0; i < 8; i++) {
                float4 kv = *(const float4*)(&Ks[j][c * 4 + 32 * i]);
                part += qreg[i*4+0]*kv.x + qreg[i*4+1]*kv.y
                      + qreg[i*4+2]*kv.z + qreg[i*4+3]*kv.w;
            }
            part += __shfl_down_sync(0xffffffffu, part, 4, 8);
            part += __shfl_down_sync(0xffffffffu, part, 2, 8);
            part += __shfl_down_sync(0xffffffffu, part, 1, 8);
            float s = __shfl_sync(0xffffffffu, part, 0, 8);
            s = SOFTCAP * tanhf(s * SCALING * (1.0f / SOFTCAP));
            int kk = kt + j;
            bool ok = (kk <= qq) && (qq - kk < WINDOW);
            s = ok ? s : -INFINITY;
            sc[j] = s;
            tmax = fmaxf(tmax, s);
        }

        float mnew = fmaxf(m, tmax);
        if (mnew != -INFINITY) {
            float alpha = (m == -INFINITY) ? 0.f : expf(m - mnew);
            float rowsum = 0.f;
#pragma unroll
            for (int j = 0; j < TK; j++) {
                float pv = (sc[j] == -INFINITY) ? 0.f : expf(sc[j] - mnew);
                sc[j] = pv;
                rowsum += pv;
            }
            l = l * alpha + rowsum;
            m = mnew;
#pragma unroll
            for (int i = 0; i < 32; i++) acc[i] *= alpha;
#pragma unroll
            for (int j = 0; j < TK; j++) {
                float pv = sc[j];
#pragma unroll
                for (int i = 0; i < 8; i++) {
                    float4 vv = *(const float4*)(&Vs[j][c * 4 + 32 * i]);
                    acc[i*4+0] += pv * vv.x;
                    acc[i*4+1] += pv * vv.y;
                    acc[i*4+2] += pv * vv.z;
                    acc[i*4+3] += pv * vv.w;
                }
            }
        }
    }

    float invl = 1.f / l;
    float* orow = o + ((size_t)(b * S_LEN + qq)) * QCOLS + h * DH;
#pragma unroll
    for (int i = 0; i < 8; i++) {
        float4 t = make_float4(acc[i*4+0]*invl, acc[i*4+1]*invl,
                               acc[i*4+2]*invl, acc[i*4+3]*invl);
        *(float4*)(orow + c * 4 + 32 * i) = t;
    }
}

// ---------------------------------------------------------------------------
// Launch
// ---------------------------------------------------------------------------
extern "C" void kernel_launch(void* const* d_in, const int* in_sizes, int n_in,
                              void* d_out, int out_size) {
    const float* hs  = (const float*)d_in[0];
    const float* Wq  = (const float*)d_in[1];
    const float* Wk  = (const float*)d_in[2];
    const float* Wv  = (const float*)d_in[3];
    const float* Wo  = (const float*)d_in[4];
    const int*   pos = (const int*)d_in[5];
    float* out = (float*)d_out;

    float *qp, *kp, *vp, *aop, *csp, *snp;
    cudaGetSymbolAddress((void**)&qp,  g_q);
    cudaGetSymbolAddress((void**)&kp,  g_k);
    cudaGetSymbolAddress((void**)&vp,  g_v);
    cudaGetSymbolAddress((void**)&aop, g_ao);
    cudaGetSymbolAddress((void**)&csp, g_cos);
    cudaGetSymbolAddress((void**)&snp, g_sin);

    // RoPE table
    {
        int total = S_LEN * (DH/2);
        rope_table_kernel<<<(total + 255) / 256, 256>>>(pos, csp, snp);
    }
    // Projections
    gemm_nt_kernel<<<dim3(QCOLS/128, MROWS/128), 256>>>(hs, Wq, qp, MROWS, QCOLS, HID);
    gemm_nt_kernel<<<dim3(KCOLS/128, MROWS/128), 256>>>(hs, Wk, kp, MROWS, KCOLS, HID);
    gemm_nt_kernel<<<dim3(KCOLS/128, MROWS/128), 256>>>(hs, Wv, vp, MROWS, KCOLS, HID);
    // RoPE
    {
        int totq = MROWS * NH * 128;
        rope_apply_kernel<<<(totq + 255) / 256, 256>>>(qp, csp, snp, NH);
        int totk = MROWS * NKVH * 128;
        rope_apply_kernel<<<(totk + 255) / 256, 256>>>(kp, csp, snp, NKVH);
    }
    // Attention
    attn_kernel<<<dim3(S_LEN/TQ, NH, BB), 256>>>(qp, kp, vp, aop);
    // Output projection
    gemm_nt_kernel<<<dim3(HID/128, MROWS/128), 256>>>(aop, Wo, out, MROWS, HID, QCOLS);
}

// round 4
// speedup vs baseline: 1.4883x; 1.4883x over previous
#include <cuda_runtime.h>
#include <cuda_bf16.h>
#include <math.h>
#include <stdint.h>

// Problem constants
#define BB    2
#define S_LEN 2048
#define HID   2304
#define NH    8
#define NKVH  4
#define DH    256
#define MROWS (BB * S_LEN)        // 4096
#define QCOLS (NH * DH)           // 2048
#define KCOLS (NKVH * DH)         // 1024
#define WINDOW 1024
#define SCALING 0.0625f           // 256^-0.5
#define SOFTCAP 50.0f

// Scratch (static device globals; no runtime allocation allowed)
__device__ float g_q [(size_t)MROWS * QCOLS];   // 32 MB
__device__ float g_k [(size_t)MROWS * KCOLS];   // 16 MB
__device__ float g_v [(size_t)MROWS * KCOLS];   // 16 MB
__device__ float g_ao[(size_t)MROWS * QCOLS];   // 32 MB
__device__ float g_cos[S_LEN * (DH/2)];         // 1 MB
__device__ float g_sin[S_LEN * (DH/2)];         // 1 MB

// ============================================================================
// Helpers (all baseline sm_80/75 features — valid for plain sm_103 target)
// ============================================================================
__device__ __forceinline__ uint32_t smem_u32(const void* p) {
    uint32_t a;
    asm("{ .reg .u64 t; cvta.to.shared.u64 t, %1; cvt.u32.u64 %0, t; }"
        : "=r"(a) : "l"(p));
    return a;
}
// pack (x -> low half, y -> high half) bf16x2
__device__ __forceinline__ uint32_t pack_bf16x2(float x, float y) {
    uint32_t u;
    asm("cvt.rn.satfinite.bf16x2.f32 %0, %1, %2;" : "=r"(u) : "f"(y), "f"(x));
    return u;
}
__device__ __forceinline__ void ldsm4(uint32_t* r, uint32_t addr) {
    asm volatile("ldmatrix.sync.aligned.m8n8.x4.shared.b16 {%0,%1,%2,%3}, [%4];"
                 : "=r"(r[0]), "=r"(r[1]), "=r"(r[2]), "=r"(r[3]) : "r"(addr));
}
__device__ __forceinline__ void mma16816(float* c, const uint32_t* a, const uint32_t* b) {
    asm volatile("mma.sync.aligned.m16n8k16.row.col.f32.bf16.bf16.f32 "
                 "{%0,%1,%2,%3}, {%4,%5,%6,%7}, {%8,%9}, {%0,%1,%2,%3};"
                 : "+f"(c[0]), "+f"(c[1]), "+f"(c[2]), "+f"(c[3])
                 : "r"(a[0]), "r"(a[1]), "r"(a[2]), "r"(a[3]),
                   "r"(b[0]), "r"(b[1]));
}

// ---------------------------------------------------------------------------
// RoPE table
// ---------------------------------------------------------------------------
__global__ void rope_table_kernel(const int* __restrict__ pos,
                                  float* __restrict__ cs, float* __restrict__ sn) {
    int idx = blockIdx.x * blockDim.x + threadIdx.x;
    if (idx >= S_LEN * (DH/2)) return;
    int s = idx >> 7;
    int j = idx & 127;
    double invf = pow(10000.0, -(double)j / 128.0);
    float freq = (float)pos[s] * (float)invf;
    cs[idx] = cosf(freq);
    sn[idx] = sinf(freq);
}

// ---------------------------------------------------------------------------
// RoPE apply (in place)
// ---------------------------------------------------------------------------
__global__ void rope_apply_kernel(float* __restrict__ x,
                                  const float* __restrict__ cs,
                                  const float* __restrict__ sn, int nh) {
    int total = MROWS * nh * 128;
    int idx = blockIdx.x * blockDim.x + threadIdx.x;
    if (idx >= total) return;
    int per_row = nh * 128;
    int mrow = idx / per_row;
    int rp   = idx - mrow * per_row;
    int hh = rp >> 7;
    int j  = rp & 127;
    int s = mrow & (S_LEN - 1);
    float c  = cs[s * 128 + j];
    float sv = sn[s * 128 + j];
    size_t base = (size_t)mrow * (nh * 256) + hh * 256 + j;
    float x1 = x[base];
    float x2 = x[base + 128];
    x[base]       = x1 * c - x2 * sv;
    x[base + 128] = x2 * c + x1 * sv;
}

// ---------------------------------------------------------------------------
// Split-bf16 tensor-core GEMM (NT): C[M,N] = A[M,K] * B[N,K]^T, fp32 in/out.
// A ~ Ah+Al, B ~ Bh+Bl (bf16); C = AhBh + AhBl + AlBh, fp32 accumulators.
// CTA tile 128x128, BK=32, 256 threads (8 warps, warp tile 64x32).
// smem: 4 bf16 tiles [128 rows x 32 cols], row stride 80 B (conflict-free
// ldmatrix: row*20 mod 32 distinct over any 8 consecutive rows).
// ---------------------------------------------------------------------------
#define GBK 32
#define ROWB 80                    // bytes per smem row
#define TILEB (128 * ROWB)         // 10240 bytes per tile

__global__ __launch_bounds__(256) void gemm_mma_kernel(
    const float* __restrict__ A, const float* __restrict__ B,
    float* __restrict__ C, int M, int N, int K)
{
    __shared__ __align__(16) unsigned char sm[4 * TILEB];   // Ah, Al, Bh, Bl
    unsigned char* smAh = sm;
    unsigned char* smAl = sm + TILEB;
    unsigned char* smBh = sm + 2 * TILEB;
    unsigned char* smBl = sm + 3 * TILEB;

    int tid  = threadIdx.x;
    int wid  = tid >> 5;
    int lane = tid & 31;
    int m0 = blockIdx.y * 128;
    int n0 = blockIdx.x * 128;
    int wm = (wid & 1) * 64;       // warp m-offset
    int wn = (wid >> 1) * 32;      // warp n-offset

    float acc[4][4][4];
#pragma unroll
    for (int i = 0; i < 4; i++)
#pragma unroll
        for (int j = 0; j < 4; j++)
#pragma unroll
            for (int t = 0; t < 4; t++) acc[i][j][t] = 0.f;

    // global load mapping: 2 threads per row, 16 cols each
    int lr = tid >> 1;             // 0..127
    int kh = (tid & 1) * 16;       // 0 or 16
    const float* arow = A + (size_t)(m0 + lr) * K + kh;
    const float* brow = B + (size_t)(n0 + lr) * K + kh;
    int soff = lr * ROWB + kh * 2; // smem byte offset of this thread's span

    // ldmatrix source addresses
    uint32_t smb = smem_u32(sm);
    int alr = lane & 15;
    int akh = (lane >> 4) * 16;    // byte offset: 0 (k0-7) or 16 (k8-15)
    uint32_t aAh = smb + 0 * TILEB + (wm + alr) * ROWB + akh;
    uint32_t aAl = smb + 1 * TILEB + (wm + alr) * ROWB + akh;
    int blr = (lane & 7) + ((lane >> 4) << 3);
    int bkh = ((lane >> 3) & 1) * 16;
    uint32_t aBh = smb + 2 * TILEB + (wn + blr) * ROWB + bkh;
    uint32_t aBl = smb + 3 * TILEB + (wn + blr) * ROWB + bkh;

    int nchunks = K / GBK;
#pragma unroll 1
    for (int ch = 0; ch < nchunks; ch++) {
        const float* ap = arow + ch * GBK;
        const float* bp = brow + ch * GBK;
#pragma unroll
        for (int i = 0; i < 4; i++) {
            int off = soff + i * 8;      // 4 bf16 = 8 bytes per step
            float4 a = *(const float4*)(ap + i * 4);
            uint32_t h0 = pack_bf16x2(a.x, a.y);
            uint32_t h1 = pack_bf16x2(a.z, a.w);
            float lx = a.x - __uint_as_float(h0 << 16);
            float ly = a.y - __uint_as_float(h0 & 0xFFFF0000u);
            float lz = a.z - __uint_as_float(h1 << 16);
            float lw = a.w - __uint_as_float(h1 & 0xFFFF0000u);
            *(uint2*)(smAh + off) = make_uint2(h0, h1);
            *(uint2*)(smAl + off) = make_uint2(pack_bf16x2(lx, ly), pack_bf16x2(lz, lw));

            float4 b = *(const float4*)(bp + i * 4);
            uint32_t g0 = pack_bf16x2(b.x, b.y);
            uint32_t g1 = pack_bf16x2(b.z, b.w);
            float mx = b.x - __uint_as_float(g0 << 16);
            float my = b.y - __uint_as_float(g0 & 0xFFFF0000u);
            float mz = b.z - __uint_as_float(g1 << 16);
            float mw = b.w - __uint_as_float(g1 & 0xFFFF0000u);
            *(uint2*)(smBh + off) = make_uint2(g0, g1);
            *(uint2*)(smBl + off) = make_uint2(pack_bf16x2(mx, my), pack_bf16x2(mz, mw));
        }
        __syncthreads();

#pragma unroll
        for (int ks = 0; ks < 2; ks++) {
            uint32_t ah[4][4], al[4][4], bh[2][4], bl[2][4];
#pragma unroll
            for (int mt = 0; mt < 4; mt++) {
                ldsm4(ah[mt], aAh + mt * (16 * ROWB) + ks * 32);
                ldsm4(al[mt], aAl + mt * (16 * ROWB) + ks * 32);
            }
#pragma unroll
            for (int p = 0; p < 2; p++) {
                ldsm4(bh[p], aBh + p * (16 * ROWB) + ks * 32);
                ldsm4(bl[p], aBl + p * (16 * ROWB) + ks * 32);
            }
#pragma unroll
            for (int mt = 0; mt < 4; mt++) {
#pragma unroll
                for (int nt = 0; nt < 4; nt++) {
                    const uint32_t* bhp = &bh[nt >> 1][(nt & 1) * 2];
                    const uint32_t* blp = &bl[nt >> 1][(nt & 1) * 2];
                    mma16816(acc[mt][nt], ah[mt], bhp);
                    mma16816(acc[mt][nt], ah[mt], blp);
                    mma16816(acc[mt][nt], al[mt], bhp);
                }
            }
        }
        __syncthreads();
    }

    // epilogue
    int cr = lane >> 2;            // 0..7
    int cc = (lane & 3) * 2;
#pragma unroll
    for (int mt = 0; mt < 4; mt++) {
#pragma unroll
        for (int nt = 0; nt < 4; nt++) {
            int row = m0 + wm + mt * 16 + cr;
            int col = n0 + wn + nt * 8 + cc;
            *(float2*)(C + (size_t)row * N + col) =
                make_float2(acc[mt][nt][0], acc[mt][nt][1]);
            *(float2*)(C + (size_t)(row + 8) * N + col) =
                make_float2(acc[mt][nt][2], acc[mt][nt][3]);
        }
    }
}

// ---------------------------------------------------------------------------
// Flash-style sliding-window attention, fp32.
// ---------------------------------------------------------------------------
#define TQ 32
#define TK 16

__global__ __launch_bounds__(256) void attn_kernel(
    const float* __restrict__ q, const float* __restrict__ k,
    const float* __restrict__ v, float* __restrict__ o)
{
    __shared__ __align__(16) float Ks[TK][DH];
    __shared__ __align__(16) float Vs[TK][DH];

    int qt = blockIdx.x;
    int h  = blockIdx.y;
    int b  = blockIdx.z;
    int kvh = h >> 1;
    int tid = threadIdx.x;
    int lane = tid & 31, w = tid >> 5;
    int r = w * 4 + (lane >> 3);
    int c = lane & 7;
    int qq = qt * TQ + r;

    const float* qrow = q + ((size_t)(b * S_LEN + qq)) * QCOLS + h * DH;
    float qreg[32];
#pragma unroll
    for (int i = 0; i < 8; i++) {
        float4 t = *(const float4*)(qrow + c * 4 + 32 * i);
        qreg[i*4+0]=t.x; qreg[i*4+1]=t.y; qreg[i*4+2]=t.z; qreg[i*4+3]=t.w;
    }

    float acc[32];
#pragma unroll
    for (int i = 0; i < 32; i++) acc[i] = 0.f;
    float m = -INFINITY, l = 0.f;

    int q0 = qt * TQ;
    int kstart = q0 - (WINDOW - 1);
    if (kstart < 0) kstart = 0;
    kstart &= ~(TK - 1);
    int kend = q0 + TQ - 1;

#pragma unroll 1
    for (int kt = kstart; kt <= kend; kt += TK) {
        __syncthreads();
        {
            const float* kbase = k + ((size_t)(b * S_LEN + kt)) * KCOLS + kvh * DH;
            const float* vbase = v + ((size_t)(b * S_LEN + kt)) * KCOLS + kvh * DH;
#pragma unroll
            for (int p = 0; p < 4; p++) {
                int idx  = p * 256 + tid;
                int row  = idx >> 6;
                int col4 = idx & 63;
                *(float4*)(&Ks[row][col4 * 4]) =
                    *(const float4*)(kbase + (size_t)row * KCOLS + col4 * 4);
                *(float4*)(&Vs[row][col4 * 4]) =
                    *(const float4*)(vbase + (size_t)row * KCOLS + col4 * 4);
            }
        }
        __syncthreads();

        float sc[TK];
        float tmax = -INFINITY;
#pragma unroll
        for (int j = 0; j < TK; j++) {
            float part = 0.f;
#pragma unroll
            for (int i = 0; i < 8; i++) {
                float4 kv = *(const float4*)(&Ks[j][c * 4 + 32 * i]);
                part += qreg[i*4+0]*kv.x + qreg[i*4+1]*kv.y
                      + qreg[i*4+2]*kv.z + qreg[i*4+3]*kv.w;
            }
            part += __shfl_down_sync(0xffffffffu, part, 4, 8);
            part += __shfl_down_sync(0xffffffffu, part, 2, 8);
            part += __shfl_down_sync(0xffffffffu, part, 1, 8);
            float s = __shfl_sync(0xffffffffu, part, 0, 8);
            s = SOFTCAP * tanhf(s * SCALING * (1.0f / SOFTCAP));
            int kk = kt + j;
            bool ok = (kk <= qq) && (qq - kk < WINDOW);
            s = ok ? s : -INFINITY;
            sc[j] = s;
            tmax = fmaxf(tmax, s);
        }

        float mnew = fmaxf(m, tmax);
        if (mnew != -INFINITY) {
            float alpha = (m == -INFINITY) ? 0.f : __expf(m - mnew);
            float rowsum = 0.f;
#pragma unroll
            for (int j = 0; j < TK; j++) {
                float pv = (sc[j] == -INFINITY) ? 0.f : __expf(sc[j] - mnew);
                sc[j] = pv;
                rowsum += pv;
            }
            l = l * alpha + rowsum;
            m = mnew;
#pragma unroll
            for (int i = 0; i < 32; i++) acc[i] *= alpha;
#pragma unroll
            for (int j = 0; j < TK; j++) {
                float pv = sc[j];
#pragma unroll
                for (int i = 0; i < 8; i++) {
                    float4 vv = *(const float4*)(&Vs[j][c * 4 + 32 * i]);
                    acc[i*4+0] += pv * vv.x;
                    acc[i*4+1] += pv * vv.y;
                    acc[i*4+2] += pv * vv.z;
                    acc[i*4+3] += pv * vv.w;
                }
            }
        }
    }

    float invl = 1.f / l;
    float* orow = o + ((size_t)(b * S_LEN + qq)) * QCOLS + h * DH;
#pragma unroll
    for (int i = 0; i < 8; i++) {
        float4 t = make_float4(acc[i*4+0]*invl, acc[i*4+1]*invl,
                               acc[i*4+2]*invl, acc[i*4+3]*invl);
        *(float4*)(orow + c * 4 + 32 * i) = t;
    }
}

// ---------------------------------------------------------------------------
// Launch
// ---------------------------------------------------------------------------
extern "C" void kernel_launch(void* const* d_in, const int* in_sizes, int n_in,
                              void* d_out, int out_size) {
    const float* hs  = (const float*)d_in[0];
    const float* Wq  = (const float*)d_in[1];
    const float* Wk  = (const float*)d_in[2];
    const float* Wv  = (const float*)d_in[3];
    const float* Wo  = (const float*)d_in[4];
    const int*   pos = (const int*)d_in[5];
    float* out = (float*)d_out;

    float *qp, *kp, *vp, *aop, *csp, *snp;
    cudaGetSymbolAddress((void**)&qp,  g_q);
    cudaGetSymbolAddress((void**)&kp,  g_k);
    cudaGetSymbolAddress((void**)&vp,  g_v);
    cudaGetSymbolAddress((void**)&aop, g_ao);
    cudaGetSymbolAddress((void**)&csp, g_cos);
    cudaGetSymbolAddress((void**)&snp, g_sin);

    // RoPE table
    {
        int total = S_LEN * (DH/2);
        rope_table_kernel<<<(total + 255) / 256, 256>>>(pos, csp, snp);
    }
    // Projections (tensor-core split-bf16)
    gemm_mma_kernel<<<dim3(QCOLS/128, MROWS/128), 256>>>(hs, Wq, qp, MROWS, QCOLS, HID);
    gemm_mma_kernel<<<dim3(KCOLS/128, MROWS/128), 256>>>(hs, Wk, kp, MROWS, KCOLS, HID);
    gemm_mma_kernel<<<dim3(KCOLS/128, MROWS/128), 256>>>(hs, Wv, vp, MROWS, KCOLS, HID);
    // RoPE
    {
        int totq = MROWS * NH * 128;
        rope_apply_kernel<<<(totq + 255) / 256, 256>>>(qp, csp, snp, NH);
        int totk = MROWS * NKVH * 128;
        rope_apply_kernel<<<(totk + 255) / 256, 256>>>(kp, csp, snp, NKVH);
    }
    // Attention
    attn_kernel<<<dim3(S_LEN/TQ, NH, BB), 256>>>(qp, kp, vp, aop);
    // Output projection
    gemm_mma_kernel<<<dim3(HID/128, MROWS/128), 256>>>(aop, Wo, out, MROWS, HID, QCOLS);
}

// round 6
// speedup vs baseline: 2.8749x; 1.9317x over previous
#include <cuda_runtime.h>
#include <cuda_bf16.h>
#include <math.h>
#include <stdint.h>

// Problem constants
#define BB    2
#define S_LEN 2048
#define HID   2304
#define NH    8
#define NKVH  4
#define DH    256
#define MROWS (BB * S_LEN)        // 4096
#define QCOLS (NH * DH)           // 2048
#define KCOLS (NKVH * DH)         // 1024
#define WINDOW 1024
#define SCALING 0.0625f           // 256^-0.5
#define SOFTCAP 50.0f

// Scratch (static device globals; no runtime allocation allowed)
__device__ float g_q [(size_t)MROWS * QCOLS];   // 32 MB
__device__ float g_k [(size_t)MROWS * KCOLS];   // 16 MB
__device__ float g_v [(size_t)MROWS * KCOLS];   // 16 MB
__device__ float g_ao[(size_t)MROWS * QCOLS];   // 32 MB
__device__ float g_cos[S_LEN * (DH/2)];         // 1 MB
__device__ float g_sin[S_LEN * (DH/2)];         // 1 MB

// ============================================================================
// Helpers (baseline sm_80/75 features only — valid for plain sm_103 target)
// ============================================================================
__device__ __forceinline__ uint32_t smem_u32(const void* p) {
    uint32_t a;
    asm("{ .reg .u64 t; cvta.to.shared.u64 t, %1; cvt.u32.u64 %0, t; }"
        : "=r"(a) : "l"(p));
    return a;
}
// pack (x -> low half, y -> high half) bf16x2
__device__ __forceinline__ uint32_t pack_bf16x2(float x, float y) {
    uint32_t u;
    asm("cvt.rn.satfinite.bf16x2.f32 %0, %1, %2;" : "=r"(u) : "f"(y), "f"(x));
    return u;
}
__device__ __forceinline__ void ldsm4(uint32_t* r, uint32_t addr) {
    asm volatile("ldmatrix.sync.aligned.m8n8.x4.shared.b16 {%0,%1,%2,%3}, [%4];"
                 : "=r"(r[0]), "=r"(r[1]), "=r"(r[2]), "=r"(r[3]) : "r"(addr));
}
__device__ __forceinline__ void ldsm4t(uint32_t* r, uint32_t addr) {
    asm volatile("ldmatrix.sync.aligned.m8n8.x4.trans.shared.b16 {%0,%1,%2,%3}, [%4];"
                 : "=r"(r[0]), "=r"(r[1]), "=r"(r[2]), "=r"(r[3]) : "r"(addr));
}
__device__ __forceinline__ void mma16816(float* c, const uint32_t* a, const uint32_t* b) {
    asm volatile("mma.sync.aligned.m16n8k16.row.col.f32.bf16.bf16.f32 "
                 "{%0,%1,%2,%3}, {%4,%5,%6,%7}, {%8,%9}, {%0,%1,%2,%3};"
                 : "+f"(c[0]), "+f"(c[1]), "+f"(c[2]), "+f"(c[3])
                 : "r"(a[0]), "r"(a[1]), "r"(a[2]), "r"(a[3]),
                   "r"(b[0]), "r"(b[1]));
}

// ---------------------------------------------------------------------------
// RoPE table
// ---------------------------------------------------------------------------
__global__ void rope_table_kernel(const int* __restrict__ pos,
                                  float* __restrict__ cs, float* __restrict__ sn) {
    int idx = blockIdx.x * blockDim.x + threadIdx.x;
    if (idx >= S_LEN * (DH/2)) return;
    int s = idx >> 7;
    int j = idx & 127;
    double invf = pow(10000.0, -(double)j / 128.0);
    float freq = (float)pos[s] * (float)invf;
    cs[idx] = cosf(freq);
    sn[idx] = sinf(freq);
}

// ---------------------------------------------------------------------------
// RoPE apply (in place)
// ---------------------------------------------------------------------------
__global__ void rope_apply_kernel(float* __restrict__ x,
                                  const float* __restrict__ cs,
                                  const float* __restrict__ sn, int nh) {
    int total = MROWS * nh * 128;
    int idx = blockIdx.x * blockDim.x + threadIdx.x;
    if (idx >= total) return;
    int per_row = nh * 128;
    int mrow = idx / per_row;
    int rp   = idx - mrow * per_row;
    int hh = rp >> 7;
    int j  = rp & 127;
    int s = mrow & (S_LEN - 1);
    float c  = cs[s * 128 + j];
    float sv = sn[s * 128 + j];
    size_t base = (size_t)mrow * (nh * 256) + hh * 256 + j;
    float x1 = x[base];
    float x2 = x[base + 128];
    x[base]       = x1 * c - x2 * sv;
    x[base + 128] = x2 * c + x1 * sv;
}

// ---------------------------------------------------------------------------
// Split-bf16 tensor-core GEMM (NT) — unchanged (passing, rel_err 2.6e-5).
// ---------------------------------------------------------------------------
#define GBK 32
#define ROWB 80
#define TILEB (128 * ROWB)

__global__ __launch_bounds__(256) void gemm_mma_kernel(
    const float* __restrict__ A, const float* __restrict__ B,
    float* __restrict__ C, int M, int N, int K)
{
    __shared__ __align__(16) unsigned char sm[4 * TILEB];
    unsigned char* smAh = sm;
    unsigned char* smAl = sm + TILEB;
    unsigned char* smBh = sm + 2 * TILEB;
    unsigned char* smBl = sm + 3 * TILEB;

    int tid  = threadIdx.x;
    int wid  = tid >> 5;
    int lane = tid & 31;
    int m0 = blockIdx.y * 128;
    int n0 = blockIdx.x * 128;
    int wm = (wid & 1) * 64;
    int wn = (wid >> 1) * 32;

    float acc[4][4][4];
#pragma unroll
    for (int i = 0; i < 4; i++)
#pragma unroll
        for (int j = 0; j < 4; j++)
#pragma unroll
            for (int t = 0; t < 4; t++) acc[i][j][t] = 0.f;

    int lr = tid >> 1;
    int kh = (tid & 1) * 16;
    const float* arow = A + (size_t)(m0 + lr) * K + kh;
    const float* brow = B + (size_t)(n0 + lr) * K + kh;
    int soff = lr * ROWB + kh * 2;

    uint32_t smb = smem_u32(sm);
    int alr = lane & 15;
    int akh = (lane >> 4) * 16;
    uint32_t aAh = smb + 0 * TILEB + (wm + alr) * ROWB + akh;
    uint32_t aAl = smb + 1 * TILEB + (wm + alr) * ROWB + akh;
    int blr = (lane & 7) + ((lane >> 4) << 3);
    int bkh = ((lane >> 3) & 1) * 16;
    uint32_t aBh = smb + 2 * TILEB + (wn + blr) * ROWB + bkh;
    uint32_t aBl = smb + 3 * TILEB + (wn + blr) * ROWB + bkh;

    int nchunks = K / GBK;
#pragma unroll 1
    for (int ch = 0; ch < nchunks; ch++) {
        const float* ap = arow + ch * GBK;
        const float* bp = brow + ch * GBK;
#pragma unroll
        for (int i = 0; i < 4; i++) {
            int off = soff + i * 8;
            float4 a = *(const float4*)(ap + i * 4);
            uint32_t h0 = pack_bf16x2(a.x, a.y);
            uint32_t h1 = pack_bf16x2(a.z, a.w);
            float lx = a.x - __uint_as_float(h0 << 16);
            float ly = a.y - __uint_as_float(h0 & 0xFFFF0000u);
            float lz = a.z - __uint_as_float(h1 << 16);
            float lw = a.w - __uint_as_float(h1 & 0xFFFF0000u);
            *(uint2*)(smAh + off) = make_uint2(h0, h1);
            *(uint2*)(smAl + off) = make_uint2(pack_bf16x2(lx, ly), pack_bf16x2(lz, lw));

            float4 b = *(const float4*)(bp + i * 4);
            uint32_t g0 = pack_bf16x2(b.x, b.y);
            uint32_t g1 = pack_bf16x2(b.z, b.w);
            float mx = b.x - __uint_as_float(g0 << 16);
            float my = b.y - __uint_as_float(g0 & 0xFFFF0000u);
            float mz = b.z - __uint_as_float(g1 << 16);
            float mw = b.w - __uint_as_float(g1 & 0xFFFF0000u);
            *(uint2*)(smBh + off) = make_uint2(g0, g1);
            *(uint2*)(smBl + off) = make_uint2(pack_bf16x2(mx, my), pack_bf16x2(mz, mw));
        }
        __syncthreads();

#pragma unroll
        for (int ks = 0; ks < 2; ks++) {
            uint32_t ah[4][4], al[4][4], bh[2][4], bl[2][4];
#pragma unroll
            for (int mt = 0; mt < 4; mt++) {
                ldsm4(ah[mt], aAh + mt * (16 * ROWB) + ks * 32);
                ldsm4(al[mt], aAl + mt * (16 * ROWB) + ks * 32);
            }
#pragma unroll
            for (int p = 0; p < 2; p++) {
                ldsm4(bh[p], aBh + p * (16 * ROWB) + ks * 32);
                ldsm4(bl[p], aBl + p * (16 * ROWB) + ks * 32);
            }
#pragma unroll
            for (int mt = 0; mt < 4; mt++) {
#pragma unroll
                for (int nt = 0; nt < 4; nt++) {
                    const uint32_t* bhp = &bh[nt >> 1][(nt & 1) * 2];
                    const uint32_t* blp = &bl[nt >> 1][(nt & 1) * 2];
                    mma16816(acc[mt][nt], ah[mt], bhp);
                    mma16816(acc[mt][nt], ah[mt], blp);
                    mma16816(acc[mt][nt], al[mt], bhp);
                }
            }
        }
        __syncthreads();
    }

    int cr = lane >> 2;
    int cc = (lane & 3) * 2;
#pragma unroll
    for (int mt = 0; mt < 4; mt++) {
#pragma unroll
        for (int nt = 0; nt < 4; nt++) {
            int row = m0 + wm + mt * 16 + cr;
            int col = n0 + wn + nt * 8 + cc;
            *(float2*)(C + (size_t)row * N + col) =
                make_float2(acc[mt][nt][0], acc[mt][nt][1]);
            *(float2*)(C + (size_t)(row + 8) * N + col) =
                make_float2(acc[mt][nt][2], acc[mt][nt][3]);
        }
    }
}

// ---------------------------------------------------------------------------
// mma flash attention, sliding window + softcap. Full split-bf16 numerics:
// scores = QhKh+QhKl+QlKh ; PV = PhVh+PhVl+PlVh (P,V both hi/lo).
// Block: 256 thr / 8 warps; TQ=128 q rows (16 per warp); TK=16 keys per tile.
// ---------------------------------------------------------------------------
#define AQT 128
#define ATK 16
#define QSTR 528
#define KSTR 528
#define ASM_QH 0
#define ASM_QL (AQT * QSTR)                 // 67584
#define ASM_KH (2 * AQT * QSTR)             // 135168
#define ASM_KL (ASM_KH + ATK * KSTR)        // 143616
#define ASM_VH (ASM_KL + ATK * KSTR)        // 152064
#define ASM_VL (ASM_VH + ATK * KSTR)        // 160512
#define ASM_TOT (ASM_VL + ATK * KSTR)       // 168960

__global__ __launch_bounds__(256, 1) void attn_mma_kernel(
    const float* __restrict__ q, const float* __restrict__ k,
    const float* __restrict__ v, float* __restrict__ o)
{
    extern __shared__ char asmem[];
    uint32_t sb = smem_u32(asmem);
    int tid = threadIdx.x, wid = tid >> 5, lane = tid & 31;
    int qt = blockIdx.x, h = blockIdx.y, b = blockIdx.z;
    int kvh = h >> 1;
    int q0 = qt * AQT;

    // --- Load + convert Q tile into smem hi/lo (once) ---
    {
        int row = tid >> 1;
        int c0  = (tid & 1) * 128;
        const float* qrow = q + (size_t)(b * S_LEN + q0 + row) * QCOLS + h * DH + c0;
        char* dh = asmem + ASM_QH + row * QSTR + c0 * 2;
        char* dl = asmem + ASM_QL + row * QSTR + c0 * 2;
#pragma unroll
        for (int i = 0; i < 32; i++) {
            float4 a = *(const float4*)(qrow + i * 4);
            uint32_t h0 = pack_bf16x2(a.x, a.y);
            uint32_t h1 = pack_bf16x2(a.z, a.w);
            float lx = a.x - __uint_as_float(h0 << 16);
            float ly = a.y - __uint_as_float(h0 & 0xFFFF0000u);
            float lz = a.z - __uint_as_float(h1 << 16);
            float lw = a.w - __uint_as_float(h1 & 0xFFFF0000u);
            *(uint2*)(dh + i * 8) = make_uint2(h0, h1);
            *(uint2*)(dl + i * 8) = make_uint2(pack_bf16x2(lx, ly), pack_bf16x2(lz, lw));
        }
    }

    int kstart = q0 - (WINDOW - 1);
    if (kstart < 0) kstart = 0;
    kstart &= ~(ATK - 1);
    int ntiles = (q0 + AQT - 1 - kstart) / ATK + 1;

    // staging mapping: row = tid>>4 (0..15), 16 f32 per thread
    int prow = tid >> 4;
    int pcol = (tid & 15) * 16;
    const float* kbase = k + (size_t)(b * S_LEN) * KCOLS + kvh * DH;
    const float* vbase = v + (size_t)(b * S_LEN) * KCOLS + kvh * DH;

    float4 pk[4], pv[4];
    {
        const float* kr = kbase + (size_t)(kstart + prow) * KCOLS + pcol;
        const float* vr = vbase + (size_t)(kstart + prow) * KCOLS + pcol;
#pragma unroll
        for (int i = 0; i < 4; i++) { pk[i] = *(const float4*)(kr + i * 4);
                                      pv[i] = *(const float4*)(vr + i * 4); }
    }

    // ldmatrix addresses
    uint32_t aQh = sb + ASM_QH + (wid * 16 + (lane & 15)) * QSTR + (lane >> 4) * 16;
    uint32_t aQl = aQh + (ASM_QL - ASM_QH);
    uint32_t aKh = sb + ASM_KH + ((lane & 7) + ((lane >> 4) << 3)) * KSTR + ((lane >> 3) & 1) * 16;
    uint32_t aKl = aKh + (ASM_KL - ASM_KH);
    uint32_t aVh = sb + ASM_VH + ((lane & 7) + (((lane >> 3) & 1) << 3)) * KSTR + (lane >> 4) * 16;
    uint32_t aVl = aVh + (ASM_VL - ASM_VH);

    float mrow0 = -1e30f, mrow1 = -1e30f;
    float lrow0 = 0.f, lrow1 = 0.f;
    float oacc[32][4];
#pragma unroll
    for (int i = 0; i < 32; i++)
#pragma unroll
        for (int t = 0; t < 4; t++) oacc[i][t] = 0.f;

    int r0 = q0 + wid * 16 + (lane >> 2);

#pragma unroll 1
    for (int t = 0; t < ntiles; t++) {
        __syncthreads();
        // store prefetched K/V (convert fp32 -> bf16 hi/lo, both K and V)
        {
            char* kh = asmem + ASM_KH + prow * KSTR + pcol * 2;
            char* kl = asmem + ASM_KL + prow * KSTR + pcol * 2;
            char* vh = asmem + ASM_VH + prow * KSTR + pcol * 2;
            char* vl = asmem + ASM_VL + prow * KSTR + pcol * 2;
#pragma unroll
            for (int i = 0; i < 4; i++) {
                float4 a = pk[i];
                uint32_t h0 = pack_bf16x2(a.x, a.y);
                uint32_t h1 = pack_bf16x2(a.z, a.w);
                float lx = a.x - __uint_as_float(h0 << 16);
                float ly = a.y - __uint_as_float(h0 & 0xFFFF0000u);
                float lz = a.z - __uint_as_float(h1 << 16);
                float lw = a.w - __uint_as_float(h1 & 0xFFFF0000u);
                *(uint2*)(kh + i * 8) = make_uint2(h0, h1);
                *(uint2*)(kl + i * 8) = make_uint2(pack_bf16x2(lx, ly), pack_bf16x2(lz, lw));

                float4 bv = pv[i];
                uint32_t g0 = pack_bf16x2(bv.x, bv.y);
                uint32_t g1 = pack_bf16x2(bv.z, bv.w);
                float vx = bv.x - __uint_as_float(g0 << 16);
                float vy = bv.y - __uint_as_float(g0 & 0xFFFF0000u);
                float vz = bv.z - __uint_as_float(g1 << 16);
                float vw = bv.w - __uint_as_float(g1 & 0xFFFF0000u);
                *(uint2*)(vh + i * 8) = make_uint2(g0, g1);
                *(uint2*)(vl + i * 8) = make_uint2(pack_bf16x2(vx, vy), pack_bf16x2(vz, vw));
            }
        }
        __syncthreads();
        // prefetch next tile
        if (t + 1 < ntiles) {
            int kt = kstart + (t + 1) * ATK;
            const float* kr = kbase + (size_t)(kt + prow) * KCOLS + pcol;
            const float* vr = vbase + (size_t)(kt + prow) * KCOLS + pcol;
#pragma unroll
            for (int i = 0; i < 4; i++) { pk[i] = *(const float4*)(kr + i * 4);
                                          pv[i] = *(const float4*)(vr + i * 4); }
        }

        int key0 = kstart + t * ATK;
        // ---- scores ----
        float sc[2][4];
#pragma unroll
        for (int nt = 0; nt < 2; nt++)
#pragma unroll
            for (int e = 0; e < 4; e++) sc[nt][e] = 0.f;
#pragma unroll
        for (int dc = 0; dc < 16; dc++) {
            uint32_t qh[4], ql[4], kh4[4], kl4[4];
            ldsm4(qh,  aQh + dc * 32);
            ldsm4(ql,  aQl + dc * 32);
            ldsm4(kh4, aKh + dc * 32);
            ldsm4(kl4, aKl + dc * 32);
#pragma unroll
            for (int nt = 0; nt < 2; nt++) {
                mma16816(sc[nt], qh, &kh4[nt * 2]);
                mma16816(sc[nt], qh, &kl4[nt * 2]);
                mma16816(sc[nt], ql, &kh4[nt * 2]);
            }
        }
        // ---- softcap + mask ----
#pragma unroll
        for (int nt = 0; nt < 2; nt++) {
#pragma unroll
            for (int e = 0; e < 4; e++) {
                int row = r0 + (e >> 1) * 8;
                int col = key0 + nt * 8 + (lane & 3) * 2 + (e & 1);
                float u = sc[nt][e] * (SCALING / SOFTCAP);
                float eu = __expf(-2.f * fabsf(u));
                float th = __fdividef(1.f - eu, 1.f + eu);
                float s = copysignf(th, u) * SOFTCAP;
                bool ok = (col <= row) && (row - col < WINDOW);
                sc[nt][e] = ok ? s : -3.0e38f;
            }
        }
        // ---- online softmax ----
        float tm0 = fmaxf(fmaxf(sc[0][0], sc[0][1]), fmaxf(sc[1][0], sc[1][1]));
        float tm1 = fmaxf(fmaxf(sc[0][2], sc[0][3]), fmaxf(sc[1][2], sc[1][3]));
        tm0 = fmaxf(tm0, __shfl_xor_sync(0xffffffffu, tm0, 1));
        tm0 = fmaxf(tm0, __shfl_xor_sync(0xffffffffu, tm0, 2));
        tm1 = fmaxf(tm1, __shfl_xor_sync(0xffffffffu, tm1, 1));
        tm1 = fmaxf(tm1, __shfl_xor_sync(0xffffffffu, tm1, 2));
        float mnew0 = fmaxf(mrow0, tm0);
        float mnew1 = fmaxf(mrow1, tm1);
        float al0 = __expf(mrow0 - mnew0);
        float al1 = __expf(mrow1 - mnew1);
        mrow0 = mnew0; mrow1 = mnew1;
#pragma unroll
        for (int nt = 0; nt < 2; nt++) {
            sc[nt][0] = __expf(sc[nt][0] - mnew0);
            sc[nt][1] = __expf(sc[nt][1] - mnew0);
            sc[nt][2] = __expf(sc[nt][2] - mnew1);
            sc[nt][3] = __expf(sc[nt][3] - mnew1);
        }
        float rs0 = sc[0][0] + sc[0][1] + sc[1][0] + sc[1][1];
        float rs1 = sc[0][2] + sc[0][3] + sc[1][2] + sc[1][3];
        rs0 += __shfl_xor_sync(0xffffffffu, rs0, 1);
        rs0 += __shfl_xor_sync(0xffffffffu, rs0, 2);
        rs1 += __shfl_xor_sync(0xffffffffu, rs1, 1);
        rs1 += __shfl_xor_sync(0xffffffffu, rs1, 2);
        lrow0 = lrow0 * al0 + rs0;
        lrow1 = lrow1 * al1 + rs1;
        if (!__all_sync(0xffffffffu, (al0 == 1.f) & (al1 == 1.f))) {
#pragma unroll
            for (int i = 0; i < 32; i++) {
                oacc[i][0] *= al0; oacc[i][1] *= al0;
                oacc[i][2] *= al1; oacc[i][3] *= al1;
            }
        }
        // ---- P fragments hi/lo + PV (3-term split) ----
        uint32_t pa[4], pal[4];
        pa[0] = pack_bf16x2(sc[0][0], sc[0][1]);
        pa[1] = pack_bf16x2(sc[0][2], sc[0][3]);
        pa[2] = pack_bf16x2(sc[1][0], sc[1][1]);
        pa[3] = pack_bf16x2(sc[1][2], sc[1][3]);
        pal[0] = pack_bf16x2(sc[0][0] - __uint_as_float(pa[0] << 16),
                             sc[0][1] - __uint_as_float(pa[0] & 0xFFFF0000u));
        pal[1] = pack_bf16x2(sc[0][2] - __uint_as_float(pa[1] << 16),
                             sc[0][3] - __uint_as_float(pa[1] & 0xFFFF0000u));
        pal[2] = pack_bf16x2(sc[1][0] - __uint_as_float(pa[2] << 16),
                             sc[1][1] - __uint_as_float(pa[2] & 0xFFFF0000u));
        pal[3] = pack_bf16x2(sc[1][2] - __uint_as_float(pa[3] << 16),
                             sc[1][3] - __uint_as_float(pa[3] & 0xFFFF0000u));
#pragma unroll
        for (int g = 0; g < 16; g++) {
            uint32_t vbh[4], vbl[4];
            ldsm4t(vbh, aVh + g * 32);
            ldsm4t(vbl, aVl + g * 32);
            mma16816(oacc[2 * g],     pa,  &vbh[0]);
            mma16816(oacc[2 * g],     pa,  &vbl[0]);
            mma16816(oacc[2 * g],     pal, &vbh[0]);
            mma16816(oacc[2 * g + 1], pa,  &vbh[2]);
            mma16816(oacc[2 * g + 1], pa,  &vbl[2]);
            mma16816(oacc[2 * g + 1], pal, &vbh[2]);
        }
    }

    // ---- epilogue ----
    float inv0 = __fdividef(1.f, lrow0);
    float inv1 = __fdividef(1.f, lrow1);
    float* orow0 = o + (size_t)(b * S_LEN + r0) * QCOLS + h * DH;
    float* orow1 = orow0 + (size_t)8 * QCOLS;
#pragma unroll
    for (int i = 0; i < 32; i++) {
        int col = i * 8 + (lane & 3) * 2;
        *(float2*)(orow0 + col) = make_float2(oacc[i][0] * inv0, oacc[i][1] * inv0);
        *(float2*)(orow1 + col) = make_float2(oacc[i][2] * inv1, oacc[i][3] * inv1);
    }
}

// ---------------------------------------------------------------------------
// Launch
// ---------------------------------------------------------------------------
extern "C" void kernel_launch(void* const* d_in, const int* in_sizes, int n_in,
                              void* d_out, int out_size) {
    const float* hs  = (const float*)d_in[0];
    const float* Wq  = (const float*)d_in[1];
    const float* Wk  = (const float*)d_in[2];
    const float* Wv  = (const float*)d_in[3];
    const float* Wo  = (const float*)d_in[4];
    const int*   pos = (const int*)d_in[5];
    float* out = (float*)d_out;

    float *qp, *kp, *vp, *aop, *csp, *snp;
    cudaGetSymbolAddress((void**)&qp,  g_q);
    cudaGetSymbolAddress((void**)&kp,  g_k);
    cudaGetSymbolAddress((void**)&vp,  g_v);
    cudaGetSymbolAddress((void**)&aop, g_ao);
    cudaGetSymbolAddress((void**)&csp, g_cos);
    cudaGetSymbolAddress((void**)&snp, g_sin);

    cudaFuncSetAttribute(attn_mma_kernel,
                         cudaFuncAttributeMaxDynamicSharedMemorySize, ASM_TOT);

    // RoPE table
    {
        int total = S_LEN * (DH/2);
        rope_table_kernel<<<(total + 255) / 256, 256>>>(pos, csp, snp);
    }
    // Projections (tensor-core split-bf16)
    gemm_mma_kernel<<<dim3(QCOLS/128, MROWS/128), 256>>>(hs, Wq, qp, MROWS, QCOLS, HID);
    gemm_mma_kernel<<<dim3(KCOLS/128, MROWS/128), 256>>>(hs, Wk, kp, MROWS, KCOLS, HID);
    gemm_mma_kernel<<<dim3(KCOLS/128, MROWS/128), 256>>>(hs, Wv, vp, MROWS, KCOLS, HID);
    // RoPE
    {
        int totq = MROWS * NH * 128;
        rope_apply_kernel<<<(totq + 255) / 256, 256>>>(qp, csp, snp, NH);
        int totk = MROWS * NKVH * 128;
        rope_apply_kernel<<<(totk + 255) / 256, 256>>>(kp, csp, snp, NKVH);
    }
    // Attention (mma flash, full split)
    attn_mma_kernel<<<dim3(S_LEN/AQT, NH, BB), 256, ASM_TOT>>>(qp, kp, vp, aop);
    // Output projection
    gemm_mma_kernel<<<dim3(HID/128, MROWS/128), 256>>>(aop, Wo, out, MROWS, HID, QCOLS);
}

// round 7
// speedup vs baseline: 3.0803x; 1.0715x over previous
#include <cuda_runtime.h>
#include <cuda_bf16.h>
#include <math.h>
#include <stdint.h>

// Problem constants
#define BB    2
#define S_LEN 2048
#define HID   2304
#define NH    8
#define NKVH  4
#define DH    256
#define MROWS (BB * S_LEN)        // 4096
#define QCOLS (NH * DH)           // 2048
#define KCOLS (NKVH * DH)         // 1024
#define WINDOW 1024
#define SCALING 0.0625f           // 256^-0.5
#define SOFTCAP 50.0f

// Scratch (static device globals; no runtime allocation allowed)
__device__ float g_q [(size_t)MROWS * QCOLS];   // 32 MB
__device__ float g_k [(size_t)MROWS * KCOLS];   // 16 MB
__device__ float g_v [(size_t)MROWS * KCOLS];   // 16 MB
__device__ float g_ao[(size_t)MROWS * QCOLS];   // 32 MB
__device__ float g_cos[S_LEN * (DH/2)];         // 1 MB
__device__ float g_sin[S_LEN * (DH/2)];         // 1 MB

// Pre-split bf16 hi/lo buffers
__device__ __nv_bfloat16 g_hsh[(size_t)MROWS * HID];
__device__ __nv_bfloat16 g_hsl[(size_t)MROWS * HID];
__device__ __nv_bfloat16 g_wqh[(size_t)QCOLS * HID];
__device__ __nv_bfloat16 g_wql[(size_t)QCOLS * HID];
__device__ __nv_bfloat16 g_wkh[(size_t)KCOLS * HID];
__device__ __nv_bfloat16 g_wkl[(size_t)KCOLS * HID];
__device__ __nv_bfloat16 g_wvh[(size_t)KCOLS * HID];
__device__ __nv_bfloat16 g_wvl[(size_t)KCOLS * HID];
__device__ __nv_bfloat16 g_woh[(size_t)HID * QCOLS];
__device__ __nv_bfloat16 g_wol[(size_t)HID * QCOLS];
__device__ __nv_bfloat16 g_aoh[(size_t)MROWS * QCOLS];
__device__ __nv_bfloat16 g_aol[(size_t)MROWS * QCOLS];

// ============================================================================
// Helpers (baseline sm_80/75 features only — valid for plain sm_103 target)
// ============================================================================
__device__ __forceinline__ uint32_t smem_u32(const void* p) {
    uint32_t a;
    asm("{ .reg .u64 t; cvta.to.shared.u64 t, %1; cvt.u32.u64 %0, t; }"
        : "=r"(a) : "l"(p));
    return a;
}
// pack (x -> low half, y -> high half) bf16x2
__device__ __forceinline__ uint32_t pack_bf16x2(float x, float y) {
    uint32_t u;
    asm("cvt.rn.satfinite.bf16x2.f32 %0, %1, %2;" : "=r"(u) : "f"(y), "f"(x));
    return u;
}
__device__ __forceinline__ void ldsm4(uint32_t* r, uint32_t addr) {
    asm volatile("ldmatrix.sync.aligned.m8n8.x4.shared.b16 {%0,%1,%2,%3}, [%4];"
                 : "=r"(r[0]), "=r"(r[1]), "=r"(r[2]), "=r"(r[3]) : "r"(addr));
}
__device__ __forceinline__ void ldsm4t(uint32_t* r, uint32_t addr) {
    asm volatile("ldmatrix.sync.aligned.m8n8.x4.trans.shared.b16 {%0,%1,%2,%3}, [%4];"
                 : "=r"(r[0]), "=r"(r[1]), "=r"(r[2]), "=r"(r[3]) : "r"(addr));
}
__device__ __forceinline__ void mma16816(float* c, const uint32_t* a, const uint32_t* b) {
    asm volatile("mma.sync.aligned.m16n8k16.row.col.f32.bf16.bf16.f32 "
                 "{%0,%1,%2,%3}, {%4,%5,%6,%7}, {%8,%9}, {%0,%1,%2,%3};"
                 : "+f"(c[0]), "+f"(c[1]), "+f"(c[2]), "+f"(c[3])
                 : "r"(a[0]), "r"(a[1]), "r"(a[2]), "r"(a[3]),
                   "r"(b[0]), "r"(b[1]));
}
__device__ __forceinline__ void cp16(uint32_t dst, const void* src) {
    asm volatile("cp.async.ca.shared.global [%0], [%1], 16;"
                 :: "r"(dst), "l"(src) : "memory");
}
#define CP_COMMIT() asm volatile("cp.async.commit_group;" ::: "memory")
#define CP_WAIT1()  asm volatile("cp.async.wait_group 1;" ::: "memory")
#define CP_WAIT0()  asm volatile("cp.async.wait_group 0;" ::: "memory")

// ---------------------------------------------------------------------------
// Split fp32 -> bf16 hi/lo (vectorized)
// ---------------------------------------------------------------------------
__global__ void cvt_split_kernel(const float* __restrict__ x,
                                 __nv_bfloat16* __restrict__ xh,
                                 __nv_bfloat16* __restrict__ xl, int n4) {
    int i = blockIdx.x * blockDim.x + threadIdx.x;
    if (i >= n4) return;
    float4 a = ((const float4*)x)[i];
    uint32_t h0 = pack_bf16x2(a.x, a.y);
    uint32_t h1 = pack_bf16x2(a.z, a.w);
    float lx = a.x - __uint_as_float(h0 << 16);
    float ly = a.y - __uint_as_float(h0 & 0xFFFF0000u);
    float lz = a.z - __uint_as_float(h1 << 16);
    float lw = a.w - __uint_as_float(h1 & 0xFFFF0000u);
    ((uint2*)xh)[i] = make_uint2(h0, h1);
    ((uint2*)xl)[i] = make_uint2(pack_bf16x2(lx, ly), pack_bf16x2(lz, lw));
}

// ---------------------------------------------------------------------------
// RoPE table
// ---------------------------------------------------------------------------
__global__ void rope_table_kernel(const int* __restrict__ pos,
                                  float* __restrict__ cs, float* __restrict__ sn) {
    int idx = blockIdx.x * blockDim.x + threadIdx.x;
    if (idx >= S_LEN * (DH/2)) return;
    int s = idx >> 7;
    int j = idx & 127;
    double invf = pow(10000.0, -(double)j / 128.0);
    float freq = (float)pos[s] * (float)invf;
    cs[idx] = cosf(freq);
    sn[idx] = sinf(freq);
}

// ---------------------------------------------------------------------------
// RoPE apply (in place)
// ---------------------------------------------------------------------------
__global__ void rope_apply_kernel(float* __restrict__ x,
                                  const float* __restrict__ cs,
                                  const float* __restrict__ sn, int nh) {
    int total = MROWS * nh * 128;
    int idx = blockIdx.x * blockDim.x + threadIdx.x;
    if (idx >= total) return;
    int per_row = nh * 128;
    int mrow = idx / per_row;
    int rp   = idx - mrow * per_row;
    int hh = rp >> 7;
    int j  = rp & 127;
    int s = mrow & (S_LEN - 1);
    float c  = cs[s * 128 + j];
    float sv = sn[s * 128 + j];
    size_t base = (size_t)mrow * (nh * 256) + hh * 256 + j;
    float x1 = x[base];
    float x2 = x[base + 128];
    x[base]       = x1 * c - x2 * sv;
    x[base + 128] = x2 * c + x1 * sv;
}

// ---------------------------------------------------------------------------
// Split-bf16 tensor-core GEMM (NT) on pre-split inputs:
// C[M,N] = (Ah+Al)[M,K] * (Bh+Bl)[N,K]^T ≈ AhBh + AhBl + AlBh, fp32 out.
// CTA tile 128x128, BK=32, 256 threads; cp.async 2-stage double buffer.
// smem per stage: 4 tiles (Ah,Al,Bh,Bl) of 128 rows x 64 B, stride 80 B.
// ---------------------------------------------------------------------------
#define GBK 32
#define ROWB 80
#define TILEB (128 * ROWB)         // 10240
#define STAGEB (4 * TILEB)         // 40960
#define GSM_TOT (2 * STAGEB)       // 81920

__global__ __launch_bounds__(256) void gemm_bf_kernel(
    const __nv_bfloat16* __restrict__ Ah, const __nv_bfloat16* __restrict__ Al,
    const __nv_bfloat16* __restrict__ Bh, const __nv_bfloat16* __restrict__ Bl,
    float* __restrict__ C, int M, int N, int K)
{
    extern __shared__ unsigned char gsm[];
    uint32_t sb = smem_u32(gsm);

    int tid  = threadIdx.x;
    int wid  = tid >> 5;
    int lane = tid & 31;
    int m0 = blockIdx.y * 128;
    int n0 = blockIdx.x * 128;
    int wm = (wid & 1) * 64;
    int wn = (wid >> 1) * 32;

    float acc[4][4][4];
#pragma unroll
    for (int i = 0; i < 4; i++)
#pragma unroll
        for (int j = 0; j < 4; j++)
#pragma unroll
            for (int t = 0; t < 4; t++) acc[i][j][t] = 0.f;

    // copy mapping: 2 threads per row; each covers 32 B (2 x cp16)
    int lr   = tid >> 1;                 // 0..127
    int sseg = (tid & 1) * 32;           // 0 or 32 bytes within 64-B row
    const char* pAh = (const char*)(Ah + (size_t)(m0 + lr) * K) + sseg;
    const char* pAl = (const char*)(Al + (size_t)(m0 + lr) * K) + sseg;
    const char* pBh = (const char*)(Bh + (size_t)(n0 + lr) * K) + sseg;
    const char* pBl = (const char*)(Bl + (size_t)(n0 + lr) * K) + sseg;
    uint32_t dbase = sb + lr * ROWB + sseg;

    // ldmatrix addresses (stage 0)
    int alr = lane & 15;
    int akh = (lane >> 4) * 16;
    uint32_t aAh = sb + 0 * TILEB + (wm + alr) * ROWB + akh;
    uint32_t aAl = sb + 1 * TILEB + (wm + alr) * ROWB + akh;
    int blr = (lane & 7) + ((lane >> 4) << 3);
    int bkh = ((lane >> 3) & 1) * 16;
    uint32_t aBh = sb + 2 * TILEB + (wn + blr) * ROWB + bkh;
    uint32_t aBl = sb + 3 * TILEB + (wn + blr) * ROWB + bkh;

    int nchunks = K / GBK;

    // prologue: issue chunk 0 into stage 0
    {
        uint32_t d = dbase;
        cp16(d + 0 * TILEB, pAh);  cp16(d + 0 * TILEB + 16, pAh + 16);
        cp16(d + 1 * TILEB, pAl);  cp16(d + 1 * TILEB + 16, pAl + 16);
        cp16(d + 2 * TILEB, pBh);  cp16(d + 2 * TILEB + 16, pBh + 16);
        cp16(d + 3 * TILEB, pBl);  cp16(d + 3 * TILEB + 16, pBl + 16);
        CP_COMMIT();
    }

#pragma unroll 1
    for (int ch = 0; ch < nchunks; ch++) {
        int st = ch & 1;
        if (ch + 1 < nchunks) {
            uint32_t d = dbase + (st ^ 1) * STAGEB;
            size_t go = (size_t)(ch + 1) * (GBK * 2);
            cp16(d + 0 * TILEB, pAh + go);  cp16(d + 0 * TILEB + 16, pAh + go + 16);
            cp16(d + 1 * TILEB, pAl + go);  cp16(d + 1 * TILEB + 16, pAl + go + 16);
            cp16(d + 2 * TILEB, pBh + go);  cp16(d + 2 * TILEB + 16, pBh + go + 16);
            cp16(d + 3 * TILEB, pBl + go);  cp16(d + 3 * TILEB + 16, pBl + go + 16);
            CP_COMMIT();
            CP_WAIT1();
        } else {
            CP_WAIT0();
        }
        __syncthreads();

        uint32_t so = st * STAGEB;
#pragma unroll
        for (int ks = 0; ks < 2; ks++) {
            uint32_t ah[4][4], al[4][4], bh[2][4], bl[2][4];
#pragma unroll
            for (int mt = 0; mt < 4; mt++) {
                ldsm4(ah[mt], aAh + so + mt * (16 * ROWB) + ks * 32);
                ldsm4(al[mt], aAl + so + mt * (16 * ROWB) + ks * 32);
            }
#pragma unroll
            for (int p = 0; p < 2; p++) {
                ldsm4(bh[p], aBh + so + p * (16 * ROWB) + ks * 32);
                ldsm4(bl[p], aBl + so + p * (16 * ROWB) + ks * 32);
            }
#pragma unroll
            for (int mt = 0; mt < 4; mt++) {
#pragma unroll
                for (int nt = 0; nt < 4; nt++) {
                    const uint32_t* bhp = &bh[nt >> 1][(nt & 1) * 2];
                    const uint32_t* blp = &bl[nt >> 1][(nt & 1) * 2];
                    mma16816(acc[mt][nt], ah[mt], bhp);
                    mma16816(acc[mt][nt], ah[mt], blp);
                    mma16816(acc[mt][nt], al[mt], bhp);
                }
            }
        }
        __syncthreads();
    }

    int cr = lane >> 2;
    int cc = (lane & 3) * 2;
#pragma unroll
    for (int mt = 0; mt < 4; mt++) {
#pragma unroll
        for (int nt = 0; nt < 4; nt++) {
            int row = m0 + wm + mt * 16 + cr;
            int col = n0 + wn + nt * 8 + cc;
            *(float2*)(C + (size_t)row * N + col) =
                make_float2(acc[mt][nt][0], acc[mt][nt][1]);
            *(float2*)(C + (size_t)(row + 8) * N + col) =
                make_float2(acc[mt][nt][2], acc[mt][nt][3]);
        }
    }
}

// ---------------------------------------------------------------------------
// mma flash attention — unchanged from R6 (passing, rel_err 2.8e-5).
// ---------------------------------------------------------------------------
#define AQT 128
#define ATK 16
#define QSTR 528
#define KSTR 528
#define ASM_QH 0
#define ASM_QL (AQT * QSTR)
#define ASM_KH (2 * AQT * QSTR)
#define ASM_KL (ASM_KH + ATK * KSTR)
#define ASM_VH (ASM_KL + ATK * KSTR)
#define ASM_VL (ASM_VH + ATK * KSTR)
#define ASM_TOT (ASM_VL + ATK * KSTR)       // 168960

__global__ __launch_bounds__(256, 1) void attn_mma_kernel(
    const float* __restrict__ q, const float* __restrict__ k,
    const float* __restrict__ v, float* __restrict__ o)
{
    extern __shared__ char asmem[];
    uint32_t sb = smem_u32(asmem);
    int tid = threadIdx.x, wid = tid >> 5, lane = tid & 31;
    int qt = blockIdx.x, h = blockIdx.y, b = blockIdx.z;
    int kvh = h >> 1;
    int q0 = qt * AQT;

    {
        int row = tid >> 1;
        int c0  = (tid & 1) * 128;
        const float* qrow = q + (size_t)(b * S_LEN + q0 + row) * QCOLS + h * DH + c0;
        char* dh = asmem + ASM_QH + row * QSTR + c0 * 2;
        char* dl = asmem + ASM_QL + row * QSTR + c0 * 2;
#pragma unroll
        for (int i = 0; i < 32; i++) {
            float4 a = *(const float4*)(qrow + i * 4);
            uint32_t h0 = pack_bf16x2(a.x, a.y);
            uint32_t h1 = pack_bf16x2(a.z, a.w);
            float lx = a.x - __uint_as_float(h0 << 16);
            float ly = a.y - __uint_as_float(h0 & 0xFFFF0000u);
            float lz = a.z - __uint_as_float(h1 << 16);
            float lw = a.w - __uint_as_float(h1 & 0xFFFF0000u);
            *(uint2*)(dh + i * 8) = make_uint2(h0, h1);
            *(uint2*)(dl + i * 8) = make_uint2(pack_bf16x2(lx, ly), pack_bf16x2(lz, lw));
        }
    }

    int kstart = q0 - (WINDOW - 1);
    if (kstart < 0) kstart = 0;
    kstart &= ~(ATK - 1);
    int ntiles = (q0 + AQT - 1 - kstart) / ATK + 1;

    int prow = tid >> 4;
    int pcol = (tid & 15) * 16;
    const float* kbase = k + (size_t)(b * S_LEN) * KCOLS + kvh * DH;
    const float* vbase = v + (size_t)(b * S_LEN) * KCOLS + kvh * DH;

    float4 pk[4], pv[4];
    {
        const float* kr = kbase + (size_t)(kstart + prow) * KCOLS + pcol;
        const float* vr = vbase + (size_t)(kstart + prow) * KCOLS + pcol;
#pragma unroll
        for (int i = 0; i < 4; i++) { pk[i] = *(const float4*)(kr + i * 4);
                                      pv[i] = *(const float4*)(vr + i * 4); }
    }

    uint32_t aQh = sb + ASM_QH + (wid * 16 + (lane & 15)) * QSTR + (lane >> 4) * 16;
    uint32_t aQl = aQh + (ASM_QL - ASM_QH);
    uint32_t aKh = sb + ASM_KH + ((lane & 7) + ((lane >> 4) << 3)) * KSTR + ((lane >> 3) & 1) * 16;
    uint32_t aKl = aKh + (ASM_KL - ASM_KH);
    uint32_t aVh = sb + ASM_VH + ((lane & 7) + (((lane >> 3) & 1) << 3)) * KSTR + (lane >> 4) * 16;
    uint32_t aVl = aVh + (ASM_VL - ASM_VH);

    float mrow0 = -1e30f, mrow1 = -1e30f;
    float lrow0 = 0.f, lrow1 = 0.f;
    float oacc[32][4];
#pragma unroll
    for (int i = 0; i < 32; i++)
#pragma unroll
        for (int t = 0; t < 4; t++) oacc[i][t] = 0.f;

    int r0 = q0 + wid * 16 + (lane >> 2);

#pragma unroll 1
    for (int t = 0; t < ntiles; t++) {
        __syncthreads();
        {
            char* kh = asmem + ASM_KH + prow * KSTR + pcol * 2;
            char* kl = asmem + ASM_KL + prow * KSTR + pcol * 2;
            char* vh = asmem + ASM_VH + prow * KSTR + pcol * 2;
            char* vl = asmem + ASM_VL + prow * KSTR + pcol * 2;
#pragma unroll
            for (int i = 0; i < 4; i++) {
                float4 a = pk[i];
                uint32_t h0 = pack_bf16x2(a.x, a.y);
                uint32_t h1 = pack_bf16x2(a.z, a.w);
                float lx = a.x - __uint_as_float(h0 << 16);
                float ly = a.y - __uint_as_float(h0 & 0xFFFF0000u);
                float lz = a.z - __uint_as_float(h1 << 16);
                float lw = a.w - __uint_as_float(h1 & 0xFFFF0000u);
                *(uint2*)(kh + i * 8) = make_uint2(h0, h1);
                *(uint2*)(kl + i * 8) = make_uint2(pack_bf16x2(lx, ly), pack_bf16x2(lz, lw));

                float4 bv = pv[i];
                uint32_t g0 = pack_bf16x2(bv.x, bv.y);
                uint32_t g1 = pack_bf16x2(bv.z, bv.w);
                float vx = bv.x - __uint_as_float(g0 << 16);
                float vy = bv.y - __uint_as_float(g0 & 0xFFFF0000u);
                float vz = bv.z - __uint_as_float(g1 << 16);
                float vw = bv.w - __uint_as_float(g1 & 0xFFFF0000u);
                *(uint2*)(vh + i * 8) = make_uint2(g0, g1);
                *(uint2*)(vl + i * 8) = make_uint2(pack_bf16x2(vx, vy), pack_bf16x2(vz, vw));
            }
        }
        __syncthreads();
        if (t + 1 < ntiles) {
            int kt = kstart + (t + 1) * ATK;
            const float* kr = kbase + (size_t)(kt + prow) * KCOLS + pcol;
            const float* vr = vbase + (size_t)(kt + prow) * KCOLS + pcol;
#pragma unroll
            for (int i = 0; i < 4; i++) { pk[i] = *(const float4*)(kr + i * 4);
                                          pv[i] = *(const float4*)(vr + i * 4); }
        }

        int key0 = kstart + t * ATK;
        float sc[2][4];
#pragma unroll
        for (int nt = 0; nt < 2; nt++)
#pragma unroll
            for (int e = 0; e < 4; e++) sc[nt][e] = 0.f;
#pragma unroll
        for (int dc = 0; dc < 16; dc++) {
            uint32_t qh[4], ql[4], kh4[4], kl4[4];
            ldsm4(qh,  aQh + dc * 32);
            ldsm4(ql,  aQl + dc * 32);
            ldsm4(kh4, aKh + dc * 32);
            ldsm4(kl4, aKl + dc * 32);
#pragma unroll
            for (int nt = 0; nt < 2; nt++) {
                mma16816(sc[nt], qh, &kh4[nt * 2]);
                mma16816(sc[nt], qh, &kl4[nt * 2]);
                mma16816(sc[nt], ql, &kh4[nt * 2]);
            }
        }
#pragma unroll
        for (int nt = 0; nt < 2; nt++) {
#pragma unroll
            for (int e = 0; e < 4; e++) {
                int row = r0 + (e >> 1) * 8;
                int col = key0 + nt * 8 + (lane & 3) * 2 + (e & 1);
                float u = sc[nt][e] * (SCALING / SOFTCAP);
                float eu = __expf(-2.f * fabsf(u));
                float th = __fdividef(1.f - eu, 1.f + eu);
                float s = copysignf(th, u) * SOFTCAP;
                bool ok = (col <= row) && (row - col < WINDOW);
                sc[nt][e] = ok ? s : -3.0e38f;
            }
        }
        float tm0 = fmaxf(fmaxf(sc[0][0], sc[0][1]), fmaxf(sc[1][0], sc[1][1]));
        float tm1 = fmaxf(fmaxf(sc[0][2], sc[0][3]), fmaxf(sc[1][2], sc[1][3]));
        tm0 = fmaxf(tm0, __shfl_xor_sync(0xffffffffu, tm0, 1));
        tm0 = fmaxf(tm0, __shfl_xor_sync(0xffffffffu, tm0, 2));
        tm1 = fmaxf(tm1, __shfl_xor_sync(0xffffffffu, tm1, 1));
        tm1 = fmaxf(tm1, __shfl_xor_sync(0xffffffffu, tm1, 2));
        float mnew0 = fmaxf(mrow0, tm0);
        float mnew1 = fmaxf(mrow1, tm1);
        float al0 = __expf(mrow0 - mnew0);
        float al1 = __expf(mrow1 - mnew1);
        mrow0 = mnew0; mrow1 = mnew1;
#pragma unroll
        for (int nt = 0; nt < 2; nt++) {
            sc[nt][0] = __expf(sc[nt][0] - mnew0);
            sc[nt][1] = __expf(sc[nt][1] - mnew0);
            sc[nt][2] = __expf(sc[nt][2] - mnew1);
            sc[nt][3] = __expf(sc[nt][3] - mnew1);
        }
        float rs0 = sc[0][0] + sc[0][1] + sc[1][0] + sc[1][1];
        float rs1 = sc[0][2] + sc[0][3] + sc[1][2] + sc[1][3];
        rs0 += __shfl_xor_sync(0xffffffffu, rs0, 1);
        rs0 += __shfl_xor_sync(0xffffffffu, rs0, 2);
        rs1 += __shfl_xor_sync(0xffffffffu, rs1, 1);
        rs1 += __shfl_xor_sync(0xffffffffu, rs1, 2);
        lrow0 = lrow0 * al0 + rs0;
        lrow1 = lrow1 * al1 + rs1;
        if (!__all_sync(0xffffffffu, (al0 == 1.f) & (al1 == 1.f))) {
#pragma unroll
            for (int i = 0; i < 32; i++) {
                oacc[i][0] *= al0; oacc[i][1] *= al0;
                oacc[i][2] *= al1; oacc[i][3] *= al1;
            }
        }
        uint32_t pa[4], pal[4];
        pa[0] = pack_bf16x2(sc[0][0], sc[0][1]);
        pa[1] = pack_bf16x2(sc[0][2], sc[0][3]);
        pa[2] = pack_bf16x2(sc[1][0], sc[1][1]);
        pa[3] = pack_bf16x2(sc[1][2], sc[1][3]);
        pal[0] = pack_bf16x2(sc[0][0] - __uint_as_float(pa[0] << 16),
                             sc[0][1] - __uint_as_float(pa[0] & 0xFFFF0000u));
        pal[1] = pack_bf16x2(sc[0][2] - __uint_as_float(pa[1] << 16),
                             sc[0][3] - __uint_as_float(pa[1] & 0xFFFF0000u));
        pal[2] = pack_bf16x2(sc[1][0] - __uint_as_float(pa[2] << 16),
                             sc[1][1] - __uint_as_float(pa[2] & 0xFFFF0000u));
        pal[3] = pack_bf16x2(sc[1][2] - __uint_as_float(pa[3] << 16),
                             sc[1][3] - __uint_as_float(pa[3] & 0xFFFF0000u));
#pragma unroll
        for (int g = 0; g < 16; g++) {
            uint32_t vbh[4], vbl[4];
            ldsm4t(vbh, aVh + g * 32);
            ldsm4t(vbl, aVl + g * 32);
            mma16816(oacc[2 * g],     pa,  &vbh[0]);
            mma16816(oacc[2 * g],     pa,  &vbl[0]);
            mma16816(oacc[2 * g],     pal, &vbh[0]);
            mma16816(oacc[2 * g + 1], pa,  &vbh[2]);
            mma16816(oacc[2 * g + 1], pa,  &vbl[2]);
            mma16816(oacc[2 * g + 1], pal, &vbh[2]);
        }
    }

    float inv0 = __fdividef(1.f, lrow0);
    float inv1 = __fdividef(1.f, lrow1);
    float* orow0 = o + (size_t)(b * S_LEN + r0) * QCOLS + h * DH;
    float* orow1 = orow0 + (size_t)8 * QCOLS;
#pragma unroll
    for (int i = 0; i < 32; i++) {
        int col = i * 8 + (lane & 3) * 2;
        *(float2*)(orow0 + col) = make_float2(oacc[i][0] * inv0, oacc[i][1] * inv0);
        *(float2*)(orow1 + col) = make_float2(oacc[i][2] * inv1, oacc[i][3] * inv1);
    }
}

// ---------------------------------------------------------------------------
// Launch
// ---------------------------------------------------------------------------
extern "C" void kernel_launch(void* const* d_in, const int* in_sizes, int n_in,
                              void* d_out, int out_size) {
    const float* hs  = (const float*)d_in[0];
    const float* Wq  = (const float*)d_in[1];
    const float* Wk  = (const float*)d_in[2];
    const float* Wv  = (const float*)d_in[3];
    const float* Wo  = (const float*)d_in[4];
    const int*   pos = (const int*)d_in[5];
    float* out = (float*)d_out;

    float *qp, *kp, *vp, *aop, *csp, *snp;
    cudaGetSymbolAddress((void**)&qp,  g_q);
    cudaGetSymbolAddress((void**)&kp,  g_k);
    cudaGetSymbolAddress((void**)&vp,  g_v);
    cudaGetSymbolAddress((void**)&aop, g_ao);
    cudaGetSymbolAddress((void**)&csp, g_cos);
    cudaGetSymbolAddress((void**)&snp, g_sin);
    __nv_bfloat16 *hsh, *hsl, *wqh, *wql, *wkh, *wkl, *wvh, *wvl, *woh, *wol, *aoh, *aol;
    cudaGetSymbolAddress((void**)&hsh, g_hsh);
    cudaGetSymbolAddress((void**)&hsl, g_hsl);
    cudaGetSymbolAddress((void**)&wqh, g_wqh);
    cudaGetSymbolAddress((void**)&wql, g_wql);
    cudaGetSymbolAddress((void**)&wkh, g_wkh);
    cudaGetSymbolAddress((void**)&wkl, g_wkl);
    cudaGetSymbolAddress((void**)&wvh, g_wvh);
    cudaGetSymbolAddress((void**)&wvl, g_wvl);
    cudaGetSymbolAddress((void**)&woh, g_woh);
    cudaGetSymbolAddress((void**)&wol, g_wol);
    cudaGetSymbolAddress((void**)&aoh, g_aoh);
    cudaGetSymbolAddress((void**)&aol, g_aol);

    cudaFuncSetAttribute(attn_mma_kernel,
                         cudaFuncAttributeMaxDynamicSharedMemorySize, ASM_TOT);
    cudaFuncSetAttribute(gemm_bf_kernel,
                         cudaFuncAttributeMaxDynamicSharedMemorySize, GSM_TOT);

    // RoPE table
    {
        int total = S_LEN * (DH/2);
        rope_table_kernel<<<(total + 255) / 256, 256>>>(pos, csp, snp);
    }
    // Pre-split inputs + weights to bf16 hi/lo
    {
        int n4;
        n4 = (MROWS * HID) / 4;
        cvt_split_kernel<<<(n4 + 255) / 256, 256>>>(hs, hsh, hsl, n4);
        n4 = (QCOLS * HID) / 4;
        cvt_split_kernel<<<(n4 + 255) / 256, 256>>>(Wq, wqh, wql, n4);
        n4 = (KCOLS * HID) / 4;
        cvt_split_kernel<<<(n4 + 255) / 256, 256>>>(Wk, wkh, wkl, n4);
        cvt_split_kernel<<<(n4 + 255) / 256, 256>>>(Wv, wvh, wvl, n4);
        n4 = (HID * QCOLS) / 4;
        cvt_split_kernel<<<(n4 + 255) / 256, 256>>>(Wo, woh, wol, n4);
    }
    // Projections (cp.async double-buffered, pre-split operands)
    gemm_bf_kernel<<<dim3(QCOLS/128, MROWS/128), 256, GSM_TOT>>>(hsh, hsl, wqh, wql, qp, MROWS, QCOLS, HID);
    gemm_bf_kernel<<<dim3(KCOLS/128, MROWS/128), 256, GSM_TOT>>>(hsh, hsl, wkh, wkl, kp, MROWS, KCOLS, HID);
    gemm_bf_kernel<<<dim3(KCOLS/128, MROWS/128), 256, GSM_TOT>>>(hsh, hsl, wvh, wvl, vp, MROWS, KCOLS, HID);
    // RoPE
    {
        int totq = MROWS * NH * 128;
        rope_apply_kernel<<<(totq + 255) / 256, 256>>>(qp, csp, snp, NH);
        int totk = MROWS * NKVH * 128;
        rope_apply_kernel<<<(totk + 255) / 256, 256>>>(kp, csp, snp, NKVH);
    }
    // Attention (mma flash, full split)
    attn_mma_kernel<<<dim3(S_LEN/AQT, NH, BB), 256, ASM_TOT>>>(qp, kp, vp, aop);
    // Split attention output, then output projection
    {
        int n4 = (MROWS * QCOLS) / 4;
        cvt_split_kernel<<<(n4 + 255) / 256, 256>>>(aop, aoh, aol, n4);
    }
    gemm_bf_kernel<<<dim3(HID/128, MROWS/128), 256, GSM_TOT>>>(aoh, aol, woh, wol, out, MROWS, HID, QCOLS);
}

// round 8
// speedup vs baseline: 3.3325x; 1.0819x over previous
#include <cuda_runtime.h>
#include <cuda_bf16.h>
#include <math.h>
#include <stdint.h>

// Problem constants
#define BB    2
#define S_LEN 2048
#define HID   2304
#define NH    8
#define NKVH  4
#define DH    256
#define MROWS (BB * S_LEN)        // 4096
#define QCOLS (NH * DH)           // 2048
#define KCOLS (NKVH * DH)         // 1024
#define WINDOW 1024
#define SCALING 0.0625f           // 256^-0.5
#define SOFTCAP 50.0f

// Scratch (static device globals; no runtime allocation allowed)
__device__ float g_q [(size_t)MROWS * QCOLS];   // 32 MB
__device__ float g_k [(size_t)MROWS * KCOLS];   // 16 MB
__device__ float g_v [(size_t)MROWS * KCOLS];   // 16 MB
__device__ float g_ao[(size_t)MROWS * QCOLS];   // 32 MB
__device__ float g_cos[S_LEN * (DH/2)];         // 1 MB
__device__ float g_sin[S_LEN * (DH/2)];         // 1 MB

// Pre-split bf16 hi/lo buffers
__device__ __nv_bfloat16 g_hsh[(size_t)MROWS * HID];
__device__ __nv_bfloat16 g_hsl[(size_t)MROWS * HID];
__device__ __nv_bfloat16 g_wqh[(size_t)QCOLS * HID];
__device__ __nv_bfloat16 g_wql[(size_t)QCOLS * HID];
__device__ __nv_bfloat16 g_wkh[(size_t)KCOLS * HID];
__device__ __nv_bfloat16 g_wkl[(size_t)KCOLS * HID];
__device__ __nv_bfloat16 g_wvh[(size_t)KCOLS * HID];
__device__ __nv_bfloat16 g_wvl[(size_t)KCOLS * HID];
__device__ __nv_bfloat16 g_woh[(size_t)HID * QCOLS];
__device__ __nv_bfloat16 g_wol[(size_t)HID * QCOLS];
__device__ __nv_bfloat16 g_aoh[(size_t)MROWS * QCOLS];
__device__ __nv_bfloat16 g_aol[(size_t)MROWS * QCOLS];

// ============================================================================
// Helpers
// ============================================================================
__device__ __forceinline__ uint32_t smem_u32(const void* p) {
    uint32_t a;
    asm("{ .reg .u64 t; cvta.to.shared.u64 t, %1; cvt.u32.u64 %0, t; }"
        : "=r"(a) : "l"(p));
    return a;
}
__device__ __forceinline__ uint32_t pack_bf16x2(float x, float y) {
    uint32_t u;
    asm("cvt.rn.satfinite.bf16x2.f32 %0, %1, %2;" : "=r"(u) : "f"(y), "f"(x));
    return u;
}
__device__ __forceinline__ void ldsm4(uint32_t* r, uint32_t addr) {
    asm volatile("ldmatrix.sync.aligned.m8n8.x4.shared.b16 {%0,%1,%2,%3}, [%4];"
                 : "=r"(r[0]), "=r"(r[1]), "=r"(r[2]), "=r"(r[3]) : "r"(addr));
}
__device__ __forceinline__ void ldsm4t(uint32_t* r, uint32_t addr) {
    asm volatile("ldmatrix.sync.aligned.m8n8.x4.trans.shared.b16 {%0,%1,%2,%3}, [%4];"
                 : "=r"(r[0]), "=r"(r[1]), "=r"(r[2]), "=r"(r[3]) : "r"(addr));
}
__device__ __forceinline__ void mma16816(float* c, const uint32_t* a, const uint32_t* b) {
    asm volatile("mma.sync.aligned.m16n8k16.row.col.f32.bf16.bf16.f32 "
                 "{%0,%1,%2,%3}, {%4,%5,%6,%7}, {%8,%9}, {%0,%1,%2,%3};"
                 : "+f"(c[0]), "+f"(c[1]), "+f"(c[2]), "+f"(c[3])
                 : "r"(a[0]), "r"(a[1]), "r"(a[2]), "r"(a[3]),
                   "r"(b[0]), "r"(b[1]));
}
__device__ __forceinline__ void cp16(uint32_t dst, const void* src) {
    asm volatile("cp.async.ca.shared.global [%0], [%1], 16;"
                 :: "r"(dst), "l"(src) : "memory");
}
#define CP_COMMIT() asm volatile("cp.async.commit_group;" ::: "memory")
#define CP_WAIT0()  asm volatile("cp.async.wait_group 0;" ::: "memory")

// ---------------------------------------------------------------------------
// Split fp32 -> bf16 hi/lo (vectorized)
// ---------------------------------------------------------------------------
__global__ void cvt_split_kernel(const float* __restrict__ x,
                                 __nv_bfloat16* __restrict__ xh,
                                 __nv_bfloat16* __restrict__ xl, int n4) {
    int i = blockIdx.x * blockDim.x + threadIdx.x;
    if (i >= n4) return;
    float4 a = ((const float4*)x)[i];
    uint32_t h0 = pack_bf16x2(a.x, a.y);
    uint32_t h1 = pack_bf16x2(a.z, a.w);
    float lx = a.x - __uint_as_float(h0 << 16);
    float ly = a.y - __uint_as_float(h0 & 0xFFFF0000u);
    float lz = a.z - __uint_as_float(h1 << 16);
    float lw = a.w - __uint_as_float(h1 & 0xFFFF0000u);
    ((uint2*)xh)[i] = make_uint2(h0, h1);
    ((uint2*)xl)[i] = make_uint2(pack_bf16x2(lx, ly), pack_bf16x2(lz, lw));
}

// ---------------------------------------------------------------------------
// RoPE table
// ---------------------------------------------------------------------------
__global__ void rope_table_kernel(const int* __restrict__ pos,
                                  float* __restrict__ cs, float* __restrict__ sn) {
    int idx = blockIdx.x * blockDim.x + threadIdx.x;
    if (idx >= S_LEN * (DH/2)) return;
    int s = idx >> 7;
    int j = idx & 127;
    double invf = pow(10000.0, -(double)j / 128.0);
    float freq = (float)pos[s] * (float)invf;
    cs[idx] = cosf(freq);
    sn[idx] = sinf(freq);
}

// ---------------------------------------------------------------------------
// RoPE apply (in place)
// ---------------------------------------------------------------------------
__global__ void rope_apply_kernel(float* __restrict__ x,
                                  const float* __restrict__ cs,
                                  const float* __restrict__ sn, int nh) {
    int total = MROWS * nh * 128;
    int idx = blockIdx.x * blockDim.x + threadIdx.x;
    if (idx >= total) return;
    int per_row = nh * 128;
    int mrow = idx / per_row;
    int rp   = idx - mrow * per_row;
    int hh = rp >> 7;
    int j  = rp & 127;
    int s = mrow & (S_LEN - 1);
    float c  = cs[s * 128 + j];
    float sv = sn[s * 128 + j];
    size_t base = (size_t)mrow * (nh * 256) + hh * 256 + j;
    float x1 = x[base];
    float x2 = x[base + 128];
    x[base]       = x1 * c - x2 * sv;
    x[base + 128] = x2 * c + x1 * sv;
}

// ---------------------------------------------------------------------------
// Split-bf16 GEMM core (NT) on pre-split inputs, single-sync 2-stage pipeline.
// C[M,N] ≈ AhBh + AhBl + AlBh, fp32 out. CTA tile 128x128, BK=32, 256 thr.
// Loop: WAIT0 -> sync -> issue cp(ch+1) -> mma(ch).  One barrier per chunk;
// copy for ch+1 overlaps the whole mma section of ch.
// ---------------------------------------------------------------------------
#define GBK 32
#define ROWB 80
#define TILEB (128 * ROWB)         // 10240
#define STAGEB (4 * TILEB)         // 40960
#define GSM_TOT (2 * STAGEB)       // 81920

__device__ __forceinline__ void gemm_core(
    const __nv_bfloat16* Ah, const __nv_bfloat16* Al,
    const __nv_bfloat16* Bh, const __nv_bfloat16* Bl,
    float* C, int m0, int n0, int N, int K, unsigned char* gsm)
{
    uint32_t sb = smem_u32(gsm);
    int tid  = threadIdx.x;
    int wid  = tid >> 5;
    int lane = tid & 31;
    int wm = (wid & 1) * 64;
    int wn = (wid >> 1) * 32;

    float acc[4][4][4];
#pragma unroll
    for (int i = 0; i < 4; i++)
#pragma unroll
        for (int j = 0; j < 4; j++)
#pragma unroll
            for (int t = 0; t < 4; t++) acc[i][j][t] = 0.f;

    int lr   = tid >> 1;
    int sseg = (tid & 1) * 32;
    const char* pAh = (const char*)(Ah + (size_t)(m0 + lr) * K) + sseg;
    const char* pAl = (const char*)(Al + (size_t)(m0 + lr) * K) + sseg;
    const char* pBh = (const char*)(Bh + (size_t)(n0 + lr) * K) + sseg;
    const char* pBl = (const char*)(Bl + (size_t)(n0 + lr) * K) + sseg;
    uint32_t dbase = sb + lr * ROWB + sseg;

    int alr = lane & 15;
    int akh = (lane >> 4) * 16;
    uint32_t aAh = sb + 0 * TILEB + (wm + alr) * ROWB + akh;
    uint32_t aAl = sb + 1 * TILEB + (wm + alr) * ROWB + akh;
    int blr = (lane & 7) + ((lane >> 4) << 3);
    int bkh = ((lane >> 3) & 1) * 16;
    uint32_t aBh = sb + 2 * TILEB + (wn + blr) * ROWB + bkh;
    uint32_t aBl = sb + 3 * TILEB + (wn + blr) * ROWB + bkh;

    int nchunks = K / GBK;

    // prologue: issue chunk 0 into stage 0
    {
        uint32_t d = dbase;
        cp16(d + 0 * TILEB, pAh);  cp16(d + 0 * TILEB + 16, pAh + 16);
        cp16(d + 1 * TILEB, pAl);  cp16(d + 1 * TILEB + 16, pAl + 16);
        cp16(d + 2 * TILEB, pBh);  cp16(d + 2 * TILEB + 16, pBh + 16);
        cp16(d + 3 * TILEB, pBl);  cp16(d + 3 * TILEB + 16, pBl + 16);
        CP_COMMIT();
    }

#pragma unroll 1
    for (int ch = 0; ch < nchunks; ch++) {
        int st = ch & 1;
        CP_WAIT0();
        __syncthreads();
        // issue next chunk into the other stage; overlaps mma below.
        if (ch + 1 < nchunks) {
            uint32_t d = dbase + (st ^ 1) * STAGEB;
            size_t go = (size_t)(ch + 1) * (GBK * 2);
            cp16(d + 0 * TILEB, pAh + go);  cp16(d + 0 * TILEB + 16, pAh + go + 16);
            cp16(d + 1 * TILEB, pAl + go);  cp16(d + 1 * TILEB + 16, pAl + go + 16);
            cp16(d + 2 * TILEB, pBh + go);  cp16(d + 2 * TILEB + 16, pBh + go + 16);
            cp16(d + 3 * TILEB, pBl + go);  cp16(d + 3 * TILEB + 16, pBl + go + 16);
        }
        CP_COMMIT();

        uint32_t so = st * STAGEB;
#pragma unroll
        for (int ks = 0; ks < 2; ks++) {
            uint32_t ah[4][4], al[4][4], bh[2][4], bl[2][4];
#pragma unroll
            for (int mt = 0; mt < 4; mt++) {
                ldsm4(ah[mt], aAh + so + mt * (16 * ROWB) + ks * 32);
                ldsm4(al[mt], aAl + so + mt * (16 * ROWB) + ks * 32);
            }
#pragma unroll
            for (int p = 0; p < 2; p++) {
                ldsm4(bh[p], aBh + so + p * (16 * ROWB) + ks * 32);
                ldsm4(bl[p], aBl + so + p * (16 * ROWB) + ks * 32);
            }
#pragma unroll
            for (int mt = 0; mt < 4; mt++) {
#pragma unroll
                for (int nt = 0; nt < 4; nt++) {
                    const uint32_t* bhp = &bh[nt >> 1][(nt & 1) * 2];
                    const uint32_t* blp = &bl[nt >> 1][(nt & 1) * 2];
                    mma16816(acc[mt][nt], ah[mt], bhp);
                    mma16816(acc[mt][nt], ah[mt], blp);
                    mma16816(acc[mt][nt], al[mt], bhp);
                }
            }
        }
    }

    int cr = lane >> 2;
    int cc = (lane & 3) * 2;
#pragma unroll
    for (int mt = 0; mt < 4; mt++) {
#pragma unroll
        for (int nt = 0; nt < 4; nt++) {
            int row = m0 + wm + mt * 16 + cr;
            int col = n0 + wn + nt * 8 + cc;
            *(float2*)(C + (size_t)row * N + col) =
                make_float2(acc[mt][nt][0], acc[mt][nt][1]);
            *(float2*)(C + (size_t)(row + 8) * N + col) =
                make_float2(acc[mt][nt][2], acc[mt][nt][3]);
        }
    }
}

// Fused QKV projection: grid.x = 32 (16 Q-tiles, 8 K, 8 V), grid.y = 32.
__global__ __launch_bounds__(256) void gemm_qkv_kernel(
    const __nv_bfloat16* __restrict__ Ah, const __nv_bfloat16* __restrict__ Al,
    const __nv_bfloat16* __restrict__ Wqh, const __nv_bfloat16* __restrict__ Wql,
    const __nv_bfloat16* __restrict__ Wkh, const __nv_bfloat16* __restrict__ Wkl,
    const __nv_bfloat16* __restrict__ Wvh, const __nv_bfloat16* __restrict__ Wvl,
    float* __restrict__ q, float* __restrict__ k, float* __restrict__ v)
{
    extern __shared__ unsigned char gsm[];
    int bx = blockIdx.x;
    int m0 = blockIdx.y * 128;
    const __nv_bfloat16 *Bh, *Bl;
    float* C;
    int n0, N;
    if (bx < 16)      { Bh = Wqh; Bl = Wql; C = q; N = QCOLS; n0 = bx * 128; }
    else if (bx < 24) { Bh = Wkh; Bl = Wkl; C = k; N = KCOLS; n0 = (bx - 16) * 128; }
    else              { Bh = Wvh; Bl = Wvl; C = v; N = KCOLS; n0 = (bx - 24) * 128; }
    gemm_core(Ah, Al, Bh, Bl, C, m0, n0, N, HID, gsm);
}

// Plain GEMM wrapper (output projection)
__global__ __launch_bounds__(256) void gemm_bf_kernel(
    const __nv_bfloat16* __restrict__ Ah, const __nv_bfloat16* __restrict__ Al,
    const __nv_bfloat16* __restrict__ Bh, const __nv_bfloat16* __restrict__ Bl,
    float* __restrict__ C, int M, int N, int K)
{
    extern __shared__ unsigned char gsm[];
    gemm_core(Ah, Al, Bh, Bl, C, blockIdx.y * 128, blockIdx.x * 128, N, K, gsm);
}

// ---------------------------------------------------------------------------
// mma flash attention — unchanged from R6/R7 (passing, rel_err 2.8e-5).
// ---------------------------------------------------------------------------
#define AQT 128
#define ATK 16
#define QSTR 528
#define KSTR 528
#define ASM_QH 0
#define ASM_QL (AQT * QSTR)
#define ASM_KH (2 * AQT * QSTR)
#define ASM_KL (ASM_KH + ATK * KSTR)
#define ASM_VH (ASM_KL + ATK * KSTR)
#define ASM_VL (ASM_VH + ATK * KSTR)
#define ASM_TOT (ASM_VL + ATK * KSTR)       // 168960

__global__ __launch_bounds__(256, 1) void attn_mma_kernel(
    const float* __restrict__ q, const float* __restrict__ k,
    const float* __restrict__ v, float* __restrict__ o)
{
    extern __shared__ char asmem[];
    uint32_t sb = smem_u32(asmem);
    int tid = threadIdx.x, wid = tid >> 5, lane = tid & 31;
    int qt = blockIdx.x, h = blockIdx.y, b = blockIdx.z;
    int kvh = h >> 1;
    int q0 = qt * AQT;

    {
        int row = tid >> 1;
        int c0  = (tid & 1) * 128;
        const float* qrow = q + (size_t)(b * S_LEN + q0 + row) * QCOLS + h * DH + c0;
        char* dh = asmem + ASM_QH + row * QSTR + c0 * 2;
        char* dl = asmem + ASM_QL + row * QSTR + c0 * 2;
#pragma unroll
        for (int i = 0; i < 32; i++) {
            float4 a = *(const float4*)(qrow + i * 4);
            uint32_t h0 = pack_bf16x2(a.x, a.y);
            uint32_t h1 = pack_bf16x2(a.z, a.w);
            float lx = a.x - __uint_as_float(h0 << 16);
            float ly = a.y - __uint_as_float(h0 & 0xFFFF0000u);
            float lz = a.z - __uint_as_float(h1 << 16);
            float lw = a.w - __uint_as_float(h1 & 0xFFFF0000u);
            *(uint2*)(dh + i * 8) = make_uint2(h0, h1);
            *(uint2*)(dl + i * 8) = make_uint2(pack_bf16x2(lx, ly), pack_bf16x2(lz, lw));
        }
    }

    int kstart = q0 - (WINDOW - 1);
    if (kstart < 0) kstart = 0;
    kstart &= ~(ATK - 1);
    int ntiles = (q0 + AQT - 1 - kstart) / ATK + 1;

    int prow = tid >> 4;
    int pcol = (tid & 15) * 16;
    const float* kbase = k + (size_t)(b * S_LEN) * KCOLS + kvh * DH;
    const float* vbase = v + (size_t)(b * S_LEN) * KCOLS + kvh * DH;

    float4 pk[4], pv[4];
    {
        const float* kr = kbase + (size_t)(kstart + prow) * KCOLS + pcol;
        const float* vr = vbase + (size_t)(kstart + prow) * KCOLS + pcol;
#pragma unroll
        for (int i = 0; i < 4; i++) { pk[i] = *(const float4*)(kr + i * 4);
                                      pv[i] = *(const float4*)(vr + i * 4); }
    }

    uint32_t aQh = sb + ASM_QH + (wid * 16 + (lane & 15)) * QSTR + (lane >> 4) * 16;
    uint32_t aQl = aQh + (ASM_QL - ASM_QH);
    uint32_t aKh = sb + ASM_KH + ((lane & 7) + ((lane >> 4) << 3)) * KSTR + ((lane >> 3) & 1) * 16;
    uint32_t aKl = aKh + (ASM_KL - ASM_KH);
    uint32_t aVh = sb + ASM_VH + ((lane & 7) + (((lane >> 3) & 1) << 3)) * KSTR + (lane >> 4) * 16;
    uint32_t aVl = aVh + (ASM_VL - ASM_VH);

    float mrow0 = -1e30f, mrow1 = -1e30f;
    float lrow0 = 0.f, lrow1 = 0.f;
    float oacc[32][4];
#pragma unroll
    for (int i = 0; i < 32; i++)
#pragma unroll
        for (int t = 0; t < 4; t++) oacc[i][t] = 0.f;

    int r0 = q0 + wid * 16 + (lane >> 2);

#pragma unroll 1
    for (int t = 0; t < ntiles; t++) {
        __syncthreads();
        {
            char* kh = asmem + ASM_KH + prow * KSTR + pcol * 2;
            char* kl = asmem + ASM_KL + prow * KSTR + pcol * 2;
            char* vh = asmem + ASM_VH + prow * KSTR + pcol * 2;
            char* vl = asmem + ASM_VL + prow * KSTR + pcol * 2;
#pragma unroll
            for (int i = 0; i < 4; i++) {
                float4 a = pk[i];
                uint32_t h0 = pack_bf16x2(a.x, a.y);
                uint32_t h1 = pack_bf16x2(a.z, a.w);
                float lx = a.x - __uint_as_float(h0 << 16);
                float ly = a.y - __uint_as_float(h0 & 0xFFFF0000u);
                float lz = a.z - __uint_as_float(h1 << 16);
                float lw = a.w - __uint_as_float(h1 & 0xFFFF0000u);
                *(uint2*)(kh + i * 8) = make_uint2(h0, h1);
                *(uint2*)(kl + i * 8) = make_uint2(pack_bf16x2(lx, ly), pack_bf16x2(lz, lw));

                float4 bv = pv[i];
                uint32_t g0 = pack_bf16x2(bv.x, bv.y);
                uint32_t g1 = pack_bf16x2(bv.z, bv.w);
                float vx = bv.x - __uint_as_float(g0 << 16);
                float vy = bv.y - __uint_as_float(g0 & 0xFFFF0000u);
                float vz = bv.z - __uint_as_float(g1 << 16);
                float vw = bv.w - __uint_as_float(g1 & 0xFFFF0000u);
                *(uint2*)(vh + i * 8) = make_uint2(g0, g1);
                *(uint2*)(vl + i * 8) = make_uint2(pack_bf16x2(vx, vy), pack_bf16x2(vz, vw));
            }
        }
        __syncthreads();
        if (t + 1 < ntiles) {
            int kt = kstart + (t + 1) * ATK;
            const float* kr = kbase + (size_t)(kt + prow) * KCOLS + pcol;
            const float* vr = vbase + (size_t)(kt + prow) * KCOLS + pcol;
#pragma unroll
            for (int i = 0; i < 4; i++) { pk[i] = *(const float4*)(kr + i * 4);
                                          pv[i] = *(const float4*)(vr + i * 4); }
        }

        int key0 = kstart + t * ATK;
        float sc[2][4];
#pragma unroll
        for (int nt = 0; nt < 2; nt++)
#pragma unroll
            for (int e = 0; e < 4; e++) sc[nt][e] = 0.f;
#pragma unroll
        for (int dc = 0; dc < 16; dc++) {
            uint32_t qh[4], ql[4], kh4[4], kl4[4];
            ldsm4(qh,  aQh + dc * 32);
            ldsm4(ql,  aQl + dc * 32);
            ldsm4(kh4, aKh + dc * 32);
            ldsm4(kl4, aKl + dc * 32);
#pragma unroll
            for (int nt = 0; nt < 2; nt++) {
                mma16816(sc[nt], qh, &kh4[nt * 2]);
                mma16816(sc[nt], qh, &kl4[nt * 2]);
                mma16816(sc[nt], ql, &kh4[nt * 2]);
            }
        }
#pragma unroll
        for (int nt = 0; nt < 2; nt++) {
#pragma unroll
            for (int e = 0; e < 4; e++) {
                int row = r0 + (e >> 1) * 8;
                int col = key0 + nt * 8 + (lane & 3) * 2 + (e & 1);
                float u = sc[nt][e] * (SCALING / SOFTCAP);
                float eu = __expf(-2.f * fabsf(u));
                float th = __fdividef(1.f - eu, 1.f + eu);
                float s = copysignf(th, u) * SOFTCAP;
                bool ok = (col <= row) && (row - col < WINDOW);
                sc[nt][e] = ok ? s : -3.0e38f;
            }
        }
        float tm0 = fmaxf(fmaxf(sc[0][0], sc[0][1]), fmaxf(sc[1][0], sc[1][1]));
        float tm1 = fmaxf(fmaxf(sc[0][2], sc[0][3]), fmaxf(sc[1][2], sc[1][3]));
        tm0 = fmaxf(tm0, __shfl_xor_sync(0xffffffffu, tm0, 1));
        tm0 = fmaxf(tm0, __shfl_xor_sync(0xffffffffu, tm0, 2));
        tm1 = fmaxf(tm1, __shfl_xor_sync(0xffffffffu, tm1, 1));
        tm1 = fmaxf(tm1, __shfl_xor_sync(0xffffffffu, tm1, 2));
        float mnew0 = fmaxf(mrow0, tm0);
        float mnew1 = fmaxf(mrow1, tm1);
        float al0 = __expf(mrow0 - mnew0);
        float al1 = __expf(mrow1 - mnew1);
        mrow0 = mnew0; mrow1 = mnew1;
#pragma unroll
        for (int nt = 0; nt < 2; nt++) {
            sc[nt][0] = __expf(sc[nt][0] - mnew0);
            sc[nt][1] = __expf(sc[nt][1] - mnew0);
            sc[nt][2] = __expf(sc[nt][2] - mnew1);
            sc[nt][3] = __expf(sc[nt][3] - mnew1);
        }
        float rs0 = sc[0][0] + sc[0][1] + sc[1][0] + sc[1][1];
        float rs1 = sc[0][2] + sc[0][3] + sc[1][2] + sc[1][3];
        rs0 += __shfl_xor_sync(0xffffffffu, rs0, 1);
        rs0 += __shfl_xor_sync(0xffffffffu, rs0, 2);
        rs1 += __shfl_xor_sync(0xffffffffu, rs1, 1);
        rs1 += __shfl_xor_sync(0xffffffffu, rs1, 2);
        lrow0 = lrow0 * al0 + rs0;
        lrow1 = lrow1 * al1 + rs1;
        if (!__all_sync(0xffffffffu, (al0 == 1.f) & (al1 == 1.f))) {
#pragma unroll
            for (int i = 0; i < 32; i++) {
                oacc[i][0] *= al0; oacc[i][1] *= al0;
                oacc[i][2] *= al1; oacc[i][3] *= al1;
            }
        }
        uint32_t pa[4], pal[4];
        pa[0] = pack_bf16x2(sc[0][0], sc[0][1]);
        pa[1] = pack_bf16x2(sc[0][2], sc[0][3]);
        pa[2] = pack_bf16x2(sc[1][0], sc[1][1]);
        pa[3] = pack_bf16x2(sc[1][2], sc[1][3]);
        pal[0] = pack_bf16x2(sc[0][0] - __uint_as_float(pa[0] << 16),
                             sc[0][1] - __uint_as_float(pa[0] & 0xFFFF0000u));
        pal[1] = pack_bf16x2(sc[0][2] - __uint_as_float(pa[1] << 16),
                             sc[0][3] - __uint_as_float(pa[1] & 0xFFFF0000u));
        pal[2] = pack_bf16x2(sc[1][0] - __uint_as_float(pa[2] << 16),
                             sc[1][1] - __uint_as_float(pa[2] & 0xFFFF0000u));
        pal[3] = pack_bf16x2(sc[1][2] - __uint_as_float(pa[3] << 16),
                             sc[1][3] - __uint_as_float(pa[3] & 0xFFFF0000u));
#pragma unroll
        for (int g = 0; g < 16; g++) {
            uint32_t vbh[4], vbl[4];
            ldsm4t(vbh, aVh + g * 32);
            ldsm4t(vbl, aVl + g * 32);
            mma16816(oacc[2 * g],     pa,  &vbh[0]);
            mma16816(oacc[2 * g],     pa,  &vbl[0]);
            mma16816(oacc[2 * g],     pal, &vbh[0]);
            mma16816(oacc[2 * g + 1], pa,  &vbh[2]);
            mma16816(oacc[2 * g + 1], pa,  &vbl[2]);
            mma16816(oacc[2 * g + 1], pal, &vbh[2]);
        }
    }

    float inv0 = __fdividef(1.f, lrow0);
    float inv1 = __fdividef(1.f, lrow1);
    float* orow0 = o + (size_t)(b * S_LEN + r0) * QCOLS + h * DH;
    float* orow1 = orow0 + (size_t)8 * QCOLS;
#pragma unroll
    for (int i = 0; i < 32; i++) {
        int col = i * 8 + (lane & 3) * 2;
        *(float2*)(orow0 + col) = make_float2(oacc[i][0] * inv0, oacc[i][1] * inv0);
        *(float2*)(orow1 + col) = make_float2(oacc[i][2] * inv1, oacc[i][3] * inv1);
    }
}

// ---------------------------------------------------------------------------
// Launch
// ---------------------------------------------------------------------------
extern "C" void kernel_launch(void* const* d_in, const int* in_sizes, int n_in,
                              void* d_out, int out_size) {
    const float* hs  = (const float*)d_in[0];
    const float* Wq  = (const float*)d_in[1];
    const float* Wk  = (const float*)d_in[2];
    const float* Wv  = (const float*)d_in[3];
    const float* Wo  = (const float*)d_in[4];
    const int*   pos = (const int*)d_in[5];
    float* out = (float*)d_out;

    float *qp, *kp, *vp, *aop, *csp, *snp;
    cudaGetSymbolAddress((void**)&qp,  g_q);
    cudaGetSymbolAddress((void**)&kp,  g_k);
    cudaGetSymbolAddress((void**)&vp,  g_v);
    cudaGetSymbolAddress((void**)&aop, g_ao);
    cudaGetSymbolAddress((void**)&csp, g_cos);
    cudaGetSymbolAddress((void**)&snp, g_sin);
    __nv_bfloat16 *hsh, *hsl, *wqh, *wql, *wkh, *wkl, *wvh, *wvl, *woh, *wol, *aoh, *aol;
    cudaGetSymbolAddress((void**)&hsh, g_hsh);
    cudaGetSymbolAddress((void**)&hsl, g_hsl);
    cudaGetSymbolAddress((void**)&wqh, g_wqh);
    cudaGetSymbolAddress((void**)&wql, g_wql);
    cudaGetSymbolAddress((void**)&wkh, g_wkh);
    cudaGetSymbolAddress((void**)&wkl, g_wkl);
    cudaGetSymbolAddress((void**)&wvh, g_wvh);
    cudaGetSymbolAddress((void**)&wvl, g_wvl);
    cudaGetSymbolAddress((void**)&woh, g_woh);
    cudaGetSymbolAddress((void**)&wol, g_wol);
    cudaGetSymbolAddress((void**)&aoh, g_aoh);
    cudaGetSymbolAddress((void**)&aol, g_aol);

    cudaFuncSetAttribute(attn_mma_kernel,
                         cudaFuncAttributeMaxDynamicSharedMemorySize, ASM_TOT);
    cudaFuncSetAttribute(gemm_bf_kernel,
                         cudaFuncAttributeMaxDynamicSharedMemorySize, GSM_TOT);
    cudaFuncSetAttribute(gemm_qkv_kernel,
                         cudaFuncAttributeMaxDynamicSharedMemorySize, GSM_TOT);

    // RoPE table
    {
        int total = S_LEN * (DH/2);
        rope_table_kernel<<<(total + 255) / 256, 256>>>(pos, csp, snp);
    }
    // Pre-split inputs + weights to bf16 hi/lo
    {
        int n4;
        n4 = (MROWS * HID) / 4;
        cvt_split_kernel<<<(n4 + 255) / 256, 256>>>(hs, hsh, hsl, n4);
        n4 = (QCOLS * HID) / 4;
        cvt_split_kernel<<<(n4 + 255) / 256, 256>>>(Wq, wqh, wql, n4);
        n4 = (KCOLS * HID) / 4;
        cvt_split_kernel<<<(n4 + 255) / 256, 256>>>(Wk, wkh, wkl, n4);
        cvt_split_kernel<<<(n4 + 255) / 256, 256>>>(Wv, wvh, wvl, n4);
        n4 = (HID * QCOLS) / 4;
        cvt_split_kernel<<<(n4 + 255) / 256, 256>>>(Wo, woh, wol, n4);
    }
    // Fused Q/K/V projections
    gemm_qkv_kernel<<<dim3(32, MROWS/128), 256, GSM_TOT>>>(
        hsh, hsl, wqh, wql, wkh, wkl, wvh, wvl, qp, kp, vp);
    // RoPE
    {
        int totq = MROWS * NH * 128;
        rope_apply_kernel<<<(totq + 255) / 256, 256>>>(qp, csp, snp, NH);
        int totk = MROWS * NKVH * 128;
        rope_apply_kernel<<<(totk + 255) / 256, 256>>>(kp, csp, snp, NKVH);
    }
    // Attention (mma flash, full split)
    attn_mma_kernel<<<dim3(S_LEN/AQT, NH, BB), 256, ASM_TOT>>>(qp, kp, vp, aop);
    // Split attention output, then output projection
    {
        int n4 = (MROWS * QCOLS) / 4;
        cvt_split_kernel<<<(n4 + 255) / 256, 256>>>(aop, aoh, aol, n4);
    }
    gemm_bf_kernel<<<dim3(HID/128, MROWS/128), 256, GSM_TOT>>>(aoh, aol, woh, wol, out, MROWS, HID, QCOLS);
}